// round 1
// baseline (speedup 1.0000x reference)
#include <cuda_runtime.h>
#include <math.h>

#define MAXT 65536
#define HD   256          // hidden size H and input size D (both 256)
#define G3   768          // 3*H
#define NR   40           // max rounds handled by the batched path

// ---------------- device scratch (static allocation only) ----------------
__device__ float g_ig[(size_t)MAXT * G3];        // igates buffer [T,768] (192MB)
__device__ int   g_starts[MAXT + 1];
__device__ int   g_len[MAXT];
__device__ int   g_sorted[MAXT];
__device__ int   g_hist[MAXT + 2];
__device__ int   g_suffix[MAXT + 2];
__device__ int   g_off[MAXT + 2];
__device__ int   g_nact[NR + 2];
__device__ int   g_nep;
__device__ int   g_start0;
__device__ __align__(16) float g_zeros[HD];      // zero-initialized, never written

// ---------------- math helpers ----------------
__device__ __forceinline__ float sigm(float x) {
    x = fminf(15.f, fmaxf(-15.f, x));
    return 1.f / (1.f + __expf(-x));
}
__device__ __forceinline__ float tanhs(float x) {
    x = fminf(9.f, fmaxf(-9.f, x));
    float e = __expf(-2.f * x);
    return (1.f - e) / (1.f + e);
}

// ---------------- igates GEMM: ig[t,c] = sum_k x[t,k]*Wih[c,k] + bias[c] ----------------
// grid: (T/64, 12), 256 threads, 64x64 tile, 4x4 per thread, K chunks of 16.
__global__ void __launch_bounds__(256) k_igates(const float* __restrict__ x,
                                                const float* __restrict__ Wih,
                                                const float* __restrict__ bias) {
    __shared__ __align__(16) float As[16][64];
    __shared__ __align__(16) float Bs[16][64];
    int tid  = threadIdx.x;
    int row0 = blockIdx.x * 64;
    int col0 = blockIdx.y * 64;
    int tx = tid & 15, ty = tid >> 4;
    int lr = tid >> 2;           // load row 0..63
    int lq = (tid & 3) * 4;      // k sub-offset 0,4,8,12

    const float* xrow = x   + (size_t)(row0 + lr) * HD;
    const float* wrow = Wih + (size_t)(col0 + lr) * HD;

    float acc[4][4];
#pragma unroll
    for (int i = 0; i < 4; i++)
#pragma unroll
        for (int jx = 0; jx < 4; jx++) acc[i][jx] = 0.f;

    for (int k0 = 0; k0 < HD; k0 += 16) {
        float4 av = *(const float4*)(xrow + k0 + lq);
        float4 bv = *(const float4*)(wrow + k0 + lq);
        As[lq + 0][lr] = av.x; As[lq + 1][lr] = av.y;
        As[lq + 2][lr] = av.z; As[lq + 3][lr] = av.w;
        Bs[lq + 0][lr] = bv.x; Bs[lq + 1][lr] = bv.y;
        Bs[lq + 2][lr] = bv.z; Bs[lq + 3][lr] = bv.w;
        __syncthreads();
#pragma unroll
        for (int kk = 0; kk < 16; kk++) {
            float4 a = *(const float4*)&As[kk][ty * 4];
            float4 b = *(const float4*)&Bs[kk][tx * 4];
            float aa[4] = {a.x, a.y, a.z, a.w};
            float bb[4] = {b.x, b.y, b.z, b.w};
#pragma unroll
            for (int i = 0; i < 4; i++)
#pragma unroll
                for (int jx = 0; jx < 4; jx++) acc[i][jx] = fmaf(aa[i], bb[jx], acc[i][jx]);
        }
        __syncthreads();
    }
    float4 b4 = *(const float4*)(bias + col0 + tx * 4);
    float bb[4] = {b4.x, b4.y, b4.z, b4.w};
#pragma unroll
    for (int i = 0; i < 4; i++) {
        float* orow = g_ig + (size_t)(row0 + ty * 4 + i) * G3 + col0 + tx * 4;
        float4 v = make_float4(acc[i][0] + bb[0], acc[i][1] + bb[1],
                               acc[i][2] + bb[2], acc[i][3] + bb[3]);
        *(float4*)orow = v;
    }
}

// ---------------- setup: segment episodes, counting-sort by length desc ----------------
__global__ void k_setup(const int* __restrict__ start, int T) {
    __shared__ int s_cnt[1024];
    int tid = threadIdx.x;
    int per = (T + 1023) / 1024;
    int b0 = tid * per, b1 = min(T, b0 + per);

    int c = 0;
    for (int t = b0; t < b1; t++)
        if (t == 0 || start[t] != 0) c++;
    s_cnt[tid] = c;
    __syncthreads();
    if (tid == 0) {
        int run = 0;
        for (int i = 0; i < 1024; i++) { int v = s_cnt[i]; s_cnt[i] = run; run += v; }
        g_nep = run;
        g_start0 = (start[0] != 0);
    }
    __syncthreads();
    int e = s_cnt[tid];
    for (int t = b0; t < b1; t++)
        if (t == 0 || start[t] != 0) g_starts[e++] = t;
    int nep = g_nep;
    if (tid == 0) g_starts[nep] = T;
    __syncthreads();

    // clear hist over bins [0, T+1]
    for (int b = tid; b <= T + 1; b += 1024) g_hist[b] = 0;
    __syncthreads();
    for (int e2 = tid; e2 < nep; e2 += 1024) {
        int L = g_starts[e2 + 1] - g_starts[e2];
        g_len[e2] = L;
        atomicAdd(&g_hist[L], 1);
    }
    __syncthreads();

    // suffix[b] = #episodes with len >= b, bins 0..T+1
    int NB = T + 2;
    int per2 = (NB + 1023) / 1024;
    int c0 = tid * per2, c1 = min(NB, c0 + per2);
    int s = 0;
    for (int b = c0; b < c1; b++) s += g_hist[b];
    s_cnt[tid] = s;
    __syncthreads();
    if (tid == 0) {
        int run = 0;
        for (int i = 1023; i >= 0; i--) { int v = s_cnt[i]; s_cnt[i] = run; run += v; }
    }
    __syncthreads();
    int run = s_cnt[tid];
    for (int b = c1 - 1; b >= c0; b--) {
        run += g_hist[b];
        g_suffix[b] = run;
    }
    __syncthreads();

    for (int b = tid; b <= T; b += 1024) g_off[b] = g_suffix[b + 1];
    for (int j = tid; j <= NR; j += 1024) g_nact[j] = g_suffix[j + 1];
    __syncthreads();

    for (int e2 = tid; e2 < nep; e2 += 1024) {
        int L = g_len[e2];
        int p = atomicAdd(&g_off[L], 1);
        g_sorted[p] = e2;
    }
}

// ---------------- round j: gathered GEMM [n_j,256]x[256,768] + GRU gate epilogue ------
// grid: (512, 4), 256 threads. blockIdx.y selects 64-wide i-slice; 3 gates per slice.
__global__ void __launch_bounds__(256) k_round(const float* __restrict__ state,
                                               const float* __restrict__ Whh,
                                               const float* __restrict__ bias_n,
                                               float* __restrict__ y, int j) {
    __shared__ __align__(16) float Hs[16][64];
    __shared__ __align__(16) float Ws[3][16][64];
    int nj = g_nact[j];
    int tid = threadIdx.x;
    int tx = tid & 15, ty = tid >> 4;
    int lr = tid >> 2, lq = (tid & 3) * 4;
    int i0 = blockIdx.y * 64;

    const float* w0 = Whh + (size_t)(0 * HD + i0 + lr) * HD;
    const float* w1 = Whh + (size_t)(1 * HD + i0 + lr) * HD;
    const float* w2 = Whh + (size_t)(2 * HD + i0 + lr) * HD;

    for (int mt = blockIdx.x; mt * 64 < nj; mt += gridDim.x) {
        // per-row hidden-state pointer for the load phase
        const float* hptr = g_zeros;
        int m_load = mt * 64 + lr;
        if (m_load < nj) {
            int e = g_sorted[m_load];
            int t = g_starts[e] + j;
            hptr = (j == 0) ? ((e == 0 && !g_start0) ? state : g_zeros)
                            : (y + (size_t)(t - 1) * HD);
        }

        float acc[3][4][4];
#pragma unroll
        for (int g = 0; g < 3; g++)
#pragma unroll
            for (int i = 0; i < 4; i++)
#pragma unroll
                for (int jx = 0; jx < 4; jx++) acc[g][i][jx] = 0.f;

        for (int k0 = 0; k0 < HD; k0 += 16) {
            float4 hv = *(const float4*)(hptr + k0 + lq);
            float4 a0 = *(const float4*)(w0 + k0 + lq);
            float4 a1 = *(const float4*)(w1 + k0 + lq);
            float4 a2 = *(const float4*)(w2 + k0 + lq);
            Hs[lq + 0][lr] = hv.x; Hs[lq + 1][lr] = hv.y;
            Hs[lq + 2][lr] = hv.z; Hs[lq + 3][lr] = hv.w;
            Ws[0][lq + 0][lr] = a0.x; Ws[0][lq + 1][lr] = a0.y;
            Ws[0][lq + 2][lr] = a0.z; Ws[0][lq + 3][lr] = a0.w;
            Ws[1][lq + 0][lr] = a1.x; Ws[1][lq + 1][lr] = a1.y;
            Ws[1][lq + 2][lr] = a1.z; Ws[1][lq + 3][lr] = a1.w;
            Ws[2][lq + 0][lr] = a2.x; Ws[2][lq + 1][lr] = a2.y;
            Ws[2][lq + 2][lr] = a2.z; Ws[2][lq + 3][lr] = a2.w;
            __syncthreads();
#pragma unroll
            for (int kk = 0; kk < 16; kk++) {
                float4 a  = *(const float4*)&Hs[kk][ty * 4];
                float4 br = *(const float4*)&Ws[0][kk][tx * 4];
                float4 bz = *(const float4*)&Ws[1][kk][tx * 4];
                float4 bn = *(const float4*)&Ws[2][kk][tx * 4];
                float aa[4] = {a.x, a.y, a.z, a.w};
                float rr[4] = {br.x, br.y, br.z, br.w};
                float zz[4] = {bz.x, bz.y, bz.z, bz.w};
                float nn[4] = {bn.x, bn.y, bn.z, bn.w};
#pragma unroll
                for (int i = 0; i < 4; i++)
#pragma unroll
                    for (int jx = 0; jx < 4; jx++) {
                        acc[0][i][jx] = fmaf(aa[i], rr[jx], acc[0][i][jx]);
                        acc[1][i][jx] = fmaf(aa[i], zz[jx], acc[1][i][jx]);
                        acc[2][i][jx] = fmaf(aa[i], nn[jx], acc[2][i][jx]);
                    }
            }
            __syncthreads();
        }

        float4 bn4 = *(const float4*)(bias_n + i0 + tx * 4);
        float bnv[4] = {bn4.x, bn4.y, bn4.z, bn4.w};
#pragma unroll
        for (int ii = 0; ii < 4; ii++) {
            int m = mt * 64 + ty * 4 + ii;
            if (m >= nj) continue;
            int e = g_sorted[m];
            int t = g_starts[e] + j;
            const float* hp = (j == 0) ? ((e == 0 && !g_start0) ? state : g_zeros)
                                       : (y + (size_t)(t - 1) * HD);
            const float* igrow = g_ig + (size_t)t * G3;
            float4 igr = *(const float4*)(igrow + i0 + tx * 4);
            float4 igz = *(const float4*)(igrow + HD + i0 + tx * 4);
            float4 ign = *(const float4*)(igrow + 2 * HD + i0 + tx * 4);
            float4 hp4 = *(const float4*)(hp + i0 + tx * 4);
            float igrv[4] = {igr.x, igr.y, igr.z, igr.w};
            float igzv[4] = {igz.x, igz.y, igz.z, igz.w};
            float ignv[4] = {ign.x, ign.y, ign.z, ign.w};
            float hpv[4]  = {hp4.x, hp4.y, hp4.z, hp4.w};
            float o[4];
#pragma unroll
            for (int jx = 0; jx < 4; jx++) {
                float r = sigm(igrv[jx] + acc[0][ii][jx]);
                float z = sigm(igzv[jx] + acc[1][ii][jx]);
                float n = tanhs(ignv[jx] + r * (acc[2][ii][jx] + bnv[jx]));
                o[jx] = n + z * (hpv[jx] - n);
            }
            *(float4*)(y + (size_t)t * HD + i0 + tx * 4) =
                make_float4(o[0], o[1], o[2], o[3]);
        }
    }
}

// ---------------- cleanup: episodes longer than NR (essentially never runs) ----------
__global__ void k_cleanup(const float* __restrict__ Whh,
                          const float* __restrict__ bias_n,
                          float* __restrict__ y) {
    int nover = g_nact[NR];   // #episodes with len > NR (they sit at the sorted front)
    __shared__ float h[HD];
    for (int idx = blockIdx.x; idx < nover; idx += gridDim.x) {
        int e = g_sorted[idx];
        int ts = g_starts[e], L = g_len[e];
        int i = threadIdx.x;
        for (int j = NR; j < L; j++) {
            int t = ts + j;
            h[i] = y[(size_t)(t - 1) * HD + i];
            __syncthreads();
            float sr = 0.f, sz = 0.f, sn = 0.f;
            for (int k = 0; k < HD; k++) {
                float hk = h[k];
                sr = fmaf(Whh[(size_t)i * HD + k], hk, sr);
                sz = fmaf(Whh[(size_t)(HD + i) * HD + k], hk, sz);
                sn = fmaf(Whh[(size_t)(2 * HD + i) * HD + k], hk, sn);
            }
            const float* ig = g_ig + (size_t)t * G3;
            float r = sigm(ig[i] + sr);
            float z = sigm(ig[HD + i] + sz);
            float n = tanhs(ig[2 * HD + i] + r * (sn + bias_n[i]));
            float out = n + z * (h[i] - n);
            __syncthreads();
            y[(size_t)t * HD + i] = out;
        }
        __syncthreads();
    }
}

// ---------------- tail: final_state = y[T-1] ----------------
__global__ void k_tail(float* out, int T, long long out_size) {
    long long base = (long long)T * HD;
    if (out_size >= base + HD) {
        int i = threadIdx.x;
        out[base + i] = out[base - HD + i];
    }
}

// ---------------- launch ----------------
extern "C" void kernel_launch(void* const* d_in, const int* in_sizes, int n_in,
                              void* d_out, int out_size) {
    const float* x      = (const float*)d_in[0];
    const float* state  = (const float*)d_in[1];
    const int*   start  = (const int*)d_in[2];
    // d_in[3] = next_done (unused)
    const float* Wih    = (const float*)d_in[4];
    const float* Whh    = (const float*)d_in[5];
    const float* bias   = (const float*)d_in[6];
    const float* bias_n = (const float*)d_in[7];
    float* out = (float*)d_out;

    int T = in_sizes[2];
    if (T > MAXT) T = MAXT;

    k_igates<<<dim3(T / 64, G3 / 64), 256>>>(x, Wih, bias);
    k_setup<<<1, 1024>>>(start, T);
    for (int j = 0; j < NR; j++) {
        k_round<<<dim3(512, 4), 256>>>(state, Whh, bias_n, out, j);
    }
    k_cleanup<<<16, 256>>>(Whh, bias_n, out);
    k_tail<<<1, 256>>>(out, T, (long long)out_size);
}

// round 3
// speedup vs baseline: 1.5782x; 1.5782x over previous
#include <cuda_runtime.h>
#include <cuda_bf16.h>
#include <cstdint>
#include <math.h>

#define MAXT 65536
#define HD   256
#define G3   768
#define NRA  40
#define RNDJ 6        // rounds 0..5 batched; finisher handles j>=6

// ---------------- device scratch ----------------
__device__ float g_ig[(size_t)MAXT * G3];
__device__ float g_hg[(size_t)(MAXT / 2 + 256) * G3];
__device__ __align__(16) __nv_bfloat16 g_xh[(size_t)MAXT * HD];
__device__ __align__(16) __nv_bfloat16 g_xl[(size_t)MAXT * HD];
__device__ __align__(16) __nv_bfloat16 g_wih_h[G3 * HD];
__device__ __align__(16) __nv_bfloat16 g_wih_l[G3 * HD];
__device__ __align__(16) __nv_bfloat16 g_whh_h[G3 * HD];
__device__ __align__(16) __nv_bfloat16 g_whh_l[G3 * HD];
__device__ int g_starts[MAXT + 1];
__device__ int g_len[MAXT];
__device__ int g_sorted[MAXT];
__device__ int g_hist[MAXT + 2];
__device__ int g_suffix[MAXT + 2];
__device__ int g_off[MAXT + 2];
__device__ int g_nact[NRA + 2];
__device__ int g_nep;
__device__ int g_start0;

// ---------------- math helpers ----------------
__device__ __forceinline__ float sigm(float x) {
    x = fminf(15.f, fmaxf(-15.f, x));
    return 1.f / (1.f + __expf(-x));
}
__device__ __forceinline__ float tanhs(float x) {
    x = fminf(9.f, fmaxf(-9.f, x));
    float e = __expf(-2.f * x);
    return (1.f - e) / (1.f + e);
}
__device__ __forceinline__ uint32_t smem_u32(const void* p) {
    uint32_t a;
    asm("{ .reg .u64 t; cvta.to.shared.u64 t, %1; cvt.u32.u64 %0, t; }" : "=r"(a) : "l"(p));
    return a;
}
__device__ __forceinline__ void ldsm4(uint32_t a, uint32_t& r0, uint32_t& r1,
                                      uint32_t& r2, uint32_t& r3) {
    asm volatile("ldmatrix.sync.aligned.m8n8.x4.shared.b16 {%0,%1,%2,%3}, [%4];"
                 : "=r"(r0), "=r"(r1), "=r"(r2), "=r"(r3) : "r"(a));
}
__device__ __forceinline__ void mma16816(float* c, uint32_t a0, uint32_t a1,
                                         uint32_t a2, uint32_t a3,
                                         uint32_t b0, uint32_t b1) {
    asm volatile("mma.sync.aligned.m16n8k16.row.col.f32.bf16.bf16.f32 "
                 "{%0,%1,%2,%3}, {%4,%5,%6,%7}, {%8,%9}, {%0,%1,%2,%3};"
                 : "+f"(c[0]), "+f"(c[1]), "+f"(c[2]), "+f"(c[3])
                 : "r"(a0), "r"(a1), "r"(a2), "r"(a3), "r"(b0), "r"(b1));
}

// One K=64 chunk of one split term: A chunk [128][64]bf16, B chunk [64][64]bf16,
// both SW128-swizzled (unit (r,u): off = r*128 + ((u ^ (r&7))<<4)).
__device__ __forceinline__ void mma_chunk(uint32_t a_s, uint32_t b_s,
                                          float (&acc)[2][4][4],
                                          int lane, int wm, int wn) {
    int arow = wm * 32 + (lane & 7) + (((lane >> 3) & 1) << 3);
    int aks  = (lane >> 4) & 1;
    uint32_t a0b = a_s + arow * 128;
    int axor = arow & 7;
    int brow = wn * 32 + (lane & 7) + (((lane >> 4) & 1) << 3);
    int bks  = (lane >> 3) & 1;
    uint32_t b0b = b_s + brow * 128;
    int bxor = brow & 7;
#pragma unroll
    for (int ks = 0; ks < 4; ks++) {
        uint32_t au = (uint32_t)(((2 * ks + aks) ^ axor) << 4);
        uint32_t bu = (uint32_t)(((2 * ks + bks) ^ bxor) << 4);
        uint32_t A0[4], A1[4], B0[4], B1[4];
        ldsm4(a0b + au,            A0[0], A0[1], A0[2], A0[3]);
        ldsm4(a0b + 16 * 128 + au, A1[0], A1[1], A1[2], A1[3]);
        ldsm4(b0b + bu,            B0[0], B0[1], B0[2], B0[3]);
        ldsm4(b0b + 16 * 128 + bu, B1[0], B1[1], B1[2], B1[3]);
        mma16816(acc[0][0], A0[0], A0[1], A0[2], A0[3], B0[0], B0[1]);
        mma16816(acc[0][1], A0[0], A0[1], A0[2], A0[3], B0[2], B0[3]);
        mma16816(acc[0][2], A0[0], A0[1], A0[2], A0[3], B1[0], B1[1]);
        mma16816(acc[0][3], A0[0], A0[1], A0[2], A0[3], B1[2], B1[3]);
        mma16816(acc[1][0], A1[0], A1[1], A1[2], A1[3], B0[0], B0[1]);
        mma16816(acc[1][1], A1[0], A1[1], A1[2], A1[3], B0[2], B0[3]);
        mma16816(acc[1][2], A1[0], A1[1], A1[2], A1[3], B1[0], B1[1]);
        mma16816(acc[1][3], A1[0], A1[1], A1[2], A1[3], B1[2], B1[3]);
    }
}

// smem offsets (shared by both GEMM kernels)
#define S_AH 0
#define S_AL 16384
#define S_BH 32768
#define S_BL 40960
#define IG_SMEM 49152
#define HG_T    49152
#define HG_SMEM 49664

// ---------------- split kernels ----------------
__global__ void k_split_x(const float* __restrict__ x, int n4) {
    int v = blockIdx.x * blockDim.x + threadIdx.x;
    if (v >= n4) return;
    float4 a = *(const float4*)(x + (size_t)v * 4);
    __nv_bfloat16 h0 = __float2bfloat16(a.x), h1 = __float2bfloat16(a.y);
    __nv_bfloat16 h2 = __float2bfloat16(a.z), h3 = __float2bfloat16(a.w);
    __nv_bfloat16 l0 = __float2bfloat16(a.x - __bfloat162float(h0));
    __nv_bfloat16 l1 = __float2bfloat16(a.y - __bfloat162float(h1));
    __nv_bfloat16 l2 = __float2bfloat16(a.z - __bfloat162float(h2));
    __nv_bfloat16 l3 = __float2bfloat16(a.w - __bfloat162float(h3));
    __nv_bfloat162* ph = (__nv_bfloat162*)(g_xh + (size_t)v * 4);
    __nv_bfloat162* pl = (__nv_bfloat162*)(g_xl + (size_t)v * 4);
    ph[0] = __halves2bfloat162(h0, h1); ph[1] = __halves2bfloat162(h2, h3);
    pl[0] = __halves2bfloat162(l0, l1); pl[1] = __halves2bfloat162(l2, l3);
}
__global__ void k_split_w(const float* __restrict__ wih, const float* __restrict__ whh) {
    int i = blockIdx.x * blockDim.x + threadIdx.x;
    if (i >= G3 * HD) return;
    float v = wih[i];
    __nv_bfloat16 h = __float2bfloat16(v);
    g_wih_h[i] = h;
    g_wih_l[i] = __float2bfloat16(v - __bfloat162float(h));
    float w = whh[i];
    __nv_bfloat16 hh = __float2bfloat16(w);
    g_whh_h[i] = hh;
    g_whh_l[i] = __float2bfloat16(w - __bfloat162float(hh));
}

// ---------------- setup (validated) ----------------
__global__ void k_setup(const int* __restrict__ start, int T) {
    __shared__ int s_cnt[1024];
    int tid = threadIdx.x;
    int per = (T + 1023) / 1024;
    int b0 = tid * per, b1 = min(T, b0 + per);
    int c = 0;
    for (int t = b0; t < b1; t++)
        if (t == 0 || start[t] != 0) c++;
    s_cnt[tid] = c;
    __syncthreads();
    if (tid == 0) {
        int run = 0;
        for (int i = 0; i < 1024; i++) { int v = s_cnt[i]; s_cnt[i] = run; run += v; }
        g_nep = run;
        g_start0 = (start[0] != 0);
    }
    __syncthreads();
    int e = s_cnt[tid];
    for (int t = b0; t < b1; t++)
        if (t == 0 || start[t] != 0) g_starts[e++] = t;
    int nep = g_nep;
    if (tid == 0) g_starts[nep] = T;
    __syncthreads();
    for (int b = tid; b <= T + 1; b += 1024) g_hist[b] = 0;
    __syncthreads();
    for (int e2 = tid; e2 < nep; e2 += 1024) {
        int L = g_starts[e2 + 1] - g_starts[e2];
        g_len[e2] = L;
        atomicAdd(&g_hist[L], 1);
    }
    __syncthreads();
    int NB = T + 2;
    int per2 = (NB + 1023) / 1024;
    int c0 = tid * per2, c1 = min(NB, c0 + per2);
    int s = 0;
    for (int b = c0; b < c1; b++) s += g_hist[b];
    s_cnt[tid] = s;
    __syncthreads();
    if (tid == 0) {
        int run = 0;
        for (int i = 1023; i >= 0; i--) { int v = s_cnt[i]; s_cnt[i] = run; run += v; }
    }
    __syncthreads();
    int run = s_cnt[tid];
    for (int b = c1 - 1; b >= c0; b--) { run += g_hist[b]; g_suffix[b] = run; }
    __syncthreads();
    for (int b = tid; b <= T; b += 1024) g_off[b] = g_suffix[b + 1];
    for (int j = tid; j <= NRA; j += 1024) g_nact[j] = g_suffix[j + 1];
    __syncthreads();
    for (int e2 = tid; e2 < nep; e2 += 1024) {
        int L = g_len[e2];
        int p = atomicAdd(&g_off[L], 1);
        g_sorted[p] = e2;
    }
}

// ---------------- igates GEMM: g_ig = x @ Wih^T + bias ----------------
// grid (12, T/128), 256 threads. C-tile 128x64, 8 warps = 4M x 2N.
__global__ void __launch_bounds__(256) k_ig(const float* __restrict__ bias, int T) {
    extern __shared__ __align__(128) char smem[];
    uint32_t sb = smem_u32(smem);
    int tid = threadIdx.x, lane = tid & 31, wid = tid >> 5;
    int wm = wid >> 1, wn = wid & 1;
    int n0 = blockIdx.x * 64, m0 = blockIdx.y * 128;

    float acc[2][4][4];
#pragma unroll
    for (int a = 0; a < 2; a++)
#pragma unroll
        for (int b = 0; b < 4; b++)
#pragma unroll
            for (int cdx = 0; cdx < 4; cdx++) acc[a][b][cdx] = 0.f;

#pragma unroll 1
    for (int c = 0; c < 4; c++) {
        int cb = c * 64;
#pragma unroll
        for (int v = tid; v < 1024; v += 256) {   // A: 128 rows x 8 units
            int r = v >> 3, u = v & 7;
            int row = min(m0 + r, T - 1);
            uint32_t off = (uint32_t)(r * 128 + (((u ^ (r & 7))) << 4));
            size_t src = (size_t)row * HD + cb + u * 8;
            *(uint4*)(smem + S_AH + off) = *(const uint4*)(g_xh + src);
            *(uint4*)(smem + S_AL + off) = *(const uint4*)(g_xl + src);
        }
#pragma unroll
        for (int v = tid; v < 512; v += 256) {    // B: 64 rows x 8 units
            int r = v >> 3, u = v & 7;
            uint32_t off = (uint32_t)(r * 128 + (((u ^ (r & 7))) << 4));
            size_t src = (size_t)(n0 + r) * HD + cb + u * 8;
            *(uint4*)(smem + S_BH + off) = *(const uint4*)(g_wih_h + src);
            *(uint4*)(smem + S_BL + off) = *(const uint4*)(g_wih_l + src);
        }
        __syncthreads();
        mma_chunk(sb + S_AH, sb + S_BH, acc, lane, wm, wn);
        mma_chunk(sb + S_AH, sb + S_BL, acc, lane, wm, wn);
        mma_chunk(sb + S_AL, sb + S_BH, acc, lane, wm, wn);
        __syncthreads();
    }
    // epilogue
#pragma unroll
    for (int nt = 0; nt < 4; nt++) {
        int col = n0 + wn * 32 + nt * 8 + (lane & 3) * 2;
        float b0 = bias[col], b1 = bias[col + 1];
#pragma unroll
        for (int mt = 0; mt < 2; mt++) {
            int row = m0 + wm * 32 + mt * 16 + (lane >> 2);
            if (row < T) {
                float* p0 = g_ig + (size_t)row * G3 + col;
                p0[0] = acc[mt][nt][0] + b0;
                p0[1] = acc[mt][nt][1] + b1;
            }
            if (row + 8 < T) {
                float* p1 = g_ig + (size_t)(row + 8) * G3 + col;
                p1[0] = acc[mt][nt][2] + b0;
                p1[1] = acc[mt][nt][3] + b1;
            }
        }
    }
}

// ---------------- round-j GEMM (j>=1): g_hg[m] = h_m @ Whh^T ----------------
// grid (12, ceil(maxnj/128)), 256 threads. A rows gathered from y, split on the fly.
__global__ void __launch_bounds__(256) k_hg(const float* __restrict__ y, int j) {
    extern __shared__ __align__(128) char smem[];
    uint32_t sb = smem_u32(smem);
    int* s_t = (int*)(smem + HG_T);
    int nj = g_nact[j];
    int mt0 = blockIdx.y * 128;
    if (mt0 >= nj) return;
    int tid = threadIdx.x, lane = tid & 31, wid = tid >> 5;
    int wm = wid >> 1, wn = wid & 1;
    int n0 = blockIdx.x * 64;

    if (tid < 128) {
        int m = mt0 + tid;
        s_t[tid] = (m < nj) ? (g_starts[g_sorted[m]] + j) : 1;
    }
    __syncthreads();

    float acc[2][4][4];
#pragma unroll
    for (int a = 0; a < 2; a++)
#pragma unroll
        for (int b = 0; b < 4; b++)
#pragma unroll
            for (int cdx = 0; cdx < 4; cdx++) acc[a][b][cdx] = 0.f;

#pragma unroll 1
    for (int c = 0; c < 4; c++) {
        int cb = c * 64;
#pragma unroll
        for (int v = tid; v < 1024; v += 256) {   // gather + split A
            int r = v >> 3, u = v & 7;
            const float* hp = y + (size_t)(s_t[r] - 1) * HD + cb + u * 8;
            float4 f0 = *(const float4*)(hp);
            float4 f1 = *(const float4*)(hp + 4);
            __nv_bfloat16 hi[8], lo[8];
            float fv[8] = {f0.x, f0.y, f0.z, f0.w, f1.x, f1.y, f1.z, f1.w};
#pragma unroll
            for (int q = 0; q < 8; q++) {
                hi[q] = __float2bfloat16(fv[q]);
                lo[q] = __float2bfloat16(fv[q] - __bfloat162float(hi[q]));
            }
            uint32_t off = (uint32_t)(r * 128 + (((u ^ (r & 7))) << 4));
            *(uint4*)(smem + S_AH + off) = *(const uint4*)hi;
            *(uint4*)(smem + S_AL + off) = *(const uint4*)lo;
        }
#pragma unroll
        for (int v = tid; v < 512; v += 256) {
            int r = v >> 3, u = v & 7;
            uint32_t off = (uint32_t)(r * 128 + (((u ^ (r & 7))) << 4));
            size_t src = (size_t)(n0 + r) * HD + cb + u * 8;
            *(uint4*)(smem + S_BH + off) = *(const uint4*)(g_whh_h + src);
            *(uint4*)(smem + S_BL + off) = *(const uint4*)(g_whh_l + src);
        }
        __syncthreads();
        mma_chunk(sb + S_AH, sb + S_BH, acc, lane, wm, wn);
        mma_chunk(sb + S_AH, sb + S_BL, acc, lane, wm, wn);
        mma_chunk(sb + S_AL, sb + S_BH, acc, lane, wm, wn);
        __syncthreads();
    }
#pragma unroll
    for (int nt = 0; nt < 4; nt++) {
        int col = n0 + wn * 32 + nt * 8 + (lane & 3) * 2;
#pragma unroll
        for (int mt = 0; mt < 2; mt++) {
            int m = mt0 + wm * 32 + mt * 16 + (lane >> 2);
            if (m < nj) {
                float* p = g_hg + (size_t)m * G3 + col;
                p[0] = acc[mt][nt][0]; p[1] = acc[mt][nt][1];
            }
            if (m + 8 < nj) {
                float* p = g_hg + (size_t)(m + 8) * G3 + col;
                p[0] = acc[mt][nt][2]; p[1] = acc[mt][nt][3];
            }
        }
    }
}

// ---------------- gates for round 0 (hg == 0 except possibly episode 0) ------
__global__ void __launch_bounds__(256) k_gates0(float* __restrict__ y,
                                                const float* __restrict__ state,
                                                const float* __restrict__ Whh,
                                                const float* __restrict__ bias_n) {
    int nj = g_nact[0];
    __shared__ float sh[HD];
    int i = threadIdx.x;
    for (int m = blockIdx.x; m < nj; m += gridDim.x) {
        int e = g_sorted[m];
        int t = g_starts[e];
        const float* ig = g_ig + (size_t)t * G3;
        float o;
        if (e == 0 && !g_start0) {   // h = state: compute hg row directly
            sh[i] = state[i];
            __syncthreads();
            float sr = 0.f, sz = 0.f, sn = 0.f;
            const float4* h4 = (const float4*)sh;
            const float4* w0 = (const float4*)(Whh + (size_t)i * HD);
            const float4* w1 = (const float4*)(Whh + (size_t)(HD + i) * HD);
            const float4* w2 = (const float4*)(Whh + (size_t)(2 * HD + i) * HD);
#pragma unroll 8
            for (int k = 0; k < 64; k++) {
                float4 hv = h4[k];
                float4 a = w0[k], b = w1[k], cc = w2[k];
                sr = fmaf(hv.x, a.x, sr);  sr = fmaf(hv.y, a.y, sr);
                sr = fmaf(hv.z, a.z, sr);  sr = fmaf(hv.w, a.w, sr);
                sz = fmaf(hv.x, b.x, sz);  sz = fmaf(hv.y, b.y, sz);
                sz = fmaf(hv.z, b.z, sz);  sz = fmaf(hv.w, b.w, sz);
                sn = fmaf(hv.x, cc.x, sn); sn = fmaf(hv.y, cc.y, sn);
                sn = fmaf(hv.z, cc.z, sn); sn = fmaf(hv.w, cc.w, sn);
            }
            float h = sh[i];
            float r = sigm(ig[i] + sr);
            float z = sigm(ig[HD + i] + sz);
            float n = tanhs(ig[2 * HD + i] + r * (sn + bias_n[i]));
            o = n + z * (h - n);
            __syncthreads();
        } else {                     // h = 0
            float r = sigm(ig[i]);
            float z = sigm(ig[HD + i]);
            float n = tanhs(ig[2 * HD + i] + r * bias_n[i]);
            o = n * (1.f - z);
        }
        y[(size_t)t * HD + i] = o;
    }
}

// ---------------- gates for round j>=1 ----------------
__global__ void __launch_bounds__(256) k_gates(float* __restrict__ y,
                                               const float* __restrict__ bias_n, int j) {
    int nj = g_nact[j];
    int m = blockIdx.x;
    if (m >= nj) return;
    int i = threadIdx.x;
    int t = g_starts[g_sorted[m]] + j;
    const float* ig = g_ig + (size_t)t * G3;
    const float* hg = g_hg + (size_t)m * G3;
    float h = y[(size_t)(t - 1) * HD + i];
    float r = sigm(ig[i] + hg[i]);
    float z = sigm(ig[HD + i] + hg[HD + i]);
    float n = tanhs(ig[2 * HD + i] + r * (hg[2 * HD + i] + bias_n[i]));
    y[(size_t)t * HD + i] = n + z * (h - n);
}

// ---------------- finisher: episodes with len > RNDJ ----------------
__global__ void __launch_bounds__(256) k_finish(const float* __restrict__ Whh,
                                                const float* __restrict__ bias_n,
                                                float* y) {
    int nover = g_nact[RNDJ];
    __shared__ __align__(16) float h[HD];
    int i = threadIdx.x;
    const float4* w0 = (const float4*)(Whh + (size_t)i * HD);
    const float4* w1 = (const float4*)(Whh + (size_t)(HD + i) * HD);
    const float4* w2 = (const float4*)(Whh + (size_t)(2 * HD + i) * HD);
    float bn = bias_n[i];
    for (int idx = blockIdx.x; idx < nover; idx += gridDim.x) {
        int e = g_sorted[idx];
        int ts = g_starts[e], L = g_len[e];
        for (int j = RNDJ; j < L; j++) {
            int t = ts + j;
            h[i] = y[(size_t)(t - 1) * HD + i];
            __syncthreads();
            const float4* h4 = (const float4*)h;
            float sr = 0.f, sz = 0.f, sn = 0.f;
#pragma unroll 8
            for (int k = 0; k < 64; k++) {
                float4 hv = h4[k];
                float4 a = w0[k], b = w1[k], cc = w2[k];
                sr = fmaf(hv.x, a.x, sr);  sr = fmaf(hv.y, a.y, sr);
                sr = fmaf(hv.z, a.z, sr);  sr = fmaf(hv.w, a.w, sr);
                sz = fmaf(hv.x, b.x, sz);  sz = fmaf(hv.y, b.y, sz);
                sz = fmaf(hv.z, b.z, sz);  sz = fmaf(hv.w, b.w, sz);
                sn = fmaf(hv.x, cc.x, sn); sn = fmaf(hv.y, cc.y, sn);
                sn = fmaf(hv.z, cc.z, sn); sn = fmaf(hv.w, cc.w, sn);
            }
            const float* ig = g_ig + (size_t)t * G3;
            float r = sigm(ig[i] + sr);
            float z = sigm(ig[HD + i] + sz);
            float n = tanhs(ig[2 * HD + i] + r * (sn + bn));
            float o = n + z * (h[i] - n);
            __syncthreads();
            y[(size_t)t * HD + i] = o;
        }
        __syncthreads();
    }
}

// ---------------- tail: final_state = y[T-1] ----------------
__global__ void k_tail(float* out, int T, long long out_size) {
    long long base = (long long)T * HD;
    if (out_size >= base + HD) {
        int i = threadIdx.x;
        out[base + i] = out[base - HD + i];
    }
}

// ---------------- launch ----------------
extern "C" void kernel_launch(void* const* d_in, const int* in_sizes, int n_in,
                              void* d_out, int out_size) {
    const float* x      = (const float*)d_in[0];
    const float* state  = (const float*)d_in[1];
    const int*   start  = (const int*)d_in[2];
    const float* Wih    = (const float*)d_in[4];
    const float* Whh    = (const float*)d_in[5];
    const float* bias   = (const float*)d_in[6];
    const float* bias_n = (const float*)d_in[7];
    float* out = (float*)d_out;

    int T = in_sizes[2];
    if (T > MAXT) T = MAXT;

    cudaFuncSetAttribute(k_ig, cudaFuncAttributeMaxDynamicSharedMemorySize, IG_SMEM);
    cudaFuncSetAttribute(k_hg, cudaFuncAttributeMaxDynamicSharedMemorySize, HG_SMEM);

    int n4 = T * HD / 4;
    k_split_x<<<(n4 + 255) / 256, 256>>>(x, n4);
    k_split_w<<<(G3 * HD + 255) / 256, 256>>>(Wih, Whh);
    k_setup<<<1, 1024>>>(start, T);
    k_ig<<<dim3(12, (T + 127) / 128), 256, IG_SMEM>>>(bias, T);
    k_gates0<<<2048, 256>>>(out, state, Whh, bias_n);
    for (int j = 1; j < RNDJ; j++) {
        int maxnj = T / (j + 1) + 1;
        k_hg<<<dim3(12, (maxnj + 127) / 128), 256, HG_SMEM>>>(out, j);
        k_gates<<<maxnj, 256>>>(out, bias_n, j);
    }
    k_finish<<<512, 256>>>(Whh, bias_n, out);
    k_tail<<<1, 256>>>(out, T, (long long)out_size);
}

// round 4
// speedup vs baseline: 1.7120x; 1.0848x over previous
#include <cuda_runtime.h>
#include <cuda_bf16.h>
#include <cstdint>
#include <math.h>

#define MAXT 65536
#define HD   256
#define G3   768
#define NRA  40
#define RNDJ 6        // rounds 0..5 batched; finisher handles j>=6

// ---------------- device scratch ----------------
__device__ float g_ig[(size_t)MAXT * G3];
__device__ float g_hg[(size_t)(MAXT / 2 + 256) * G3];
__device__ __align__(16) __nv_bfloat16 g_xh[(size_t)MAXT * HD];
__device__ __align__(16) __nv_bfloat16 g_xl[(size_t)MAXT * HD];
__device__ __align__(16) __nv_bfloat16 g_wih_h[G3 * HD];
__device__ __align__(16) __nv_bfloat16 g_wih_l[G3 * HD];
__device__ __align__(16) __nv_bfloat16 g_whh_h[G3 * HD];
__device__ __align__(16) __nv_bfloat16 g_whh_l[G3 * HD];
__device__ int g_starts[MAXT + 1];
__device__ int g_len[MAXT];
__device__ int g_sorted[MAXT];
__device__ int g_hist[MAXT + 2];
__device__ int g_suffix[MAXT + 2];
__device__ int g_off[MAXT + 2];
__device__ int g_nact[NRA + 2];
__device__ int g_nep;
__device__ int g_start0;

// ---------------- math helpers ----------------
__device__ __forceinline__ float sigm(float x) {
    x = fminf(15.f, fmaxf(-15.f, x));
    return 1.f / (1.f + __expf(-x));
}
__device__ __forceinline__ float tanhs(float x) {
    x = fminf(9.f, fmaxf(-9.f, x));
    float e = __expf(-2.f * x);
    return (1.f - e) / (1.f + e);
}
__device__ __forceinline__ uint32_t smem_u32(const void* p) {
    uint32_t a;
    asm("{ .reg .u64 t; cvta.to.shared.u64 t, %1; cvt.u32.u64 %0, t; }" : "=r"(a) : "l"(p));
    return a;
}
__device__ __forceinline__ void cpa16(uint32_t s, const void* g) {
    asm volatile("cp.async.cg.shared.global [%0], [%1], 16;"
                 :: "r"(s), "l"(g) : "memory");
}
#define CP_COMMIT() asm volatile("cp.async.commit_group;" ::: "memory")
#define CP_WAIT(n)  asm volatile("cp.async.wait_group %0;" :: "n"(n) : "memory")

__device__ __forceinline__ void ldsm4(uint32_t a, uint32_t& r0, uint32_t& r1,
                                      uint32_t& r2, uint32_t& r3) {
    asm volatile("ldmatrix.sync.aligned.m8n8.x4.shared.b16 {%0,%1,%2,%3}, [%4];"
                 : "=r"(r0), "=r"(r1), "=r"(r2), "=r"(r3) : "r"(a));
}
__device__ __forceinline__ void mma16816(float* c, uint32_t a0, uint32_t a1,
                                         uint32_t a2, uint32_t a3,
                                         uint32_t b0, uint32_t b1) {
    asm volatile("mma.sync.aligned.m16n8k16.row.col.f32.bf16.bf16.f32 "
                 "{%0,%1,%2,%3}, {%4,%5,%6,%7}, {%8,%9}, {%0,%1,%2,%3};"
                 : "+f"(c[0]), "+f"(c[1]), "+f"(c[2]), "+f"(c[3])
                 : "r"(a0), "r"(a1), "r"(a2), "r"(a3), "r"(b0), "r"(b1));
}

// One K=64 chunk of one split term (swizzle: off = r*128 + ((u ^ (r&7))<<4)).
__device__ __forceinline__ void mma_chunk(uint32_t a_s, uint32_t b_s,
                                          float (&acc)[2][4][4],
                                          int lane, int wm, int wn) {
    int arow = wm * 32 + (lane & 7) + (((lane >> 3) & 1) << 3);
    int aks  = (lane >> 4) & 1;
    uint32_t a0b = a_s + arow * 128;
    int axor = arow & 7;
    int brow = wn * 32 + (lane & 7) + (((lane >> 4) & 1) << 3);
    int bks  = (lane >> 3) & 1;
    uint32_t b0b = b_s + brow * 128;
    int bxor = brow & 7;
#pragma unroll
    for (int ks = 0; ks < 4; ks++) {
        uint32_t au = (uint32_t)(((2 * ks + aks) ^ axor) << 4);
        uint32_t bu = (uint32_t)(((2 * ks + bks) ^ bxor) << 4);
        uint32_t A0[4], A1[4], B0[4], B1[4];
        ldsm4(a0b + au,            A0[0], A0[1], A0[2], A0[3]);
        ldsm4(a0b + 16 * 128 + au, A1[0], A1[1], A1[2], A1[3]);
        ldsm4(b0b + bu,            B0[0], B0[1], B0[2], B0[3]);
        ldsm4(b0b + 16 * 128 + bu, B1[0], B1[1], B1[2], B1[3]);
        mma16816(acc[0][0], A0[0], A0[1], A0[2], A0[3], B0[0], B0[1]);
        mma16816(acc[0][1], A0[0], A0[1], A0[2], A0[3], B0[2], B0[3]);
        mma16816(acc[0][2], A0[0], A0[1], A0[2], A0[3], B1[0], B1[1]);
        mma16816(acc[0][3], A0[0], A0[1], A0[2], A0[3], B1[2], B1[3]);
        mma16816(acc[1][0], A1[0], A1[1], A1[2], A1[3], B0[0], B0[1]);
        mma16816(acc[1][1], A1[0], A1[1], A1[2], A1[3], B0[2], B0[3]);
        mma16816(acc[1][2], A1[0], A1[1], A1[2], A1[3], B1[0], B1[1]);
        mma16816(acc[1][3], A1[0], A1[1], A1[2], A1[3], B1[2], B1[3]);
    }
}

// ---------------- k_ig stage layout: 2 stages x 48KB ----------------
#define IGS_AH 0
#define IGS_AL 16384
#define IGS_BH 32768
#define IGS_BL 40960
#define IGS_STRIDE 49152
#define IG_SMEM (2 * IGS_STRIDE)

// ---------------- k_hg layout: 2 stages (A32 32KB + B 16KB) + conv 32KB + s_t --
#define HGS_A32 0
#define HGS_BH  32768
#define HGS_BL  40960
#define HGS_STRIDE 49152
#define HG_CAH  98304
#define HG_CAL  114688
#define HG_T    131072
#define HG_SMEM 131584

// ---------------- split kernels ----------------
__global__ void k_split_x(const float* __restrict__ x, int n4) {
    int v = blockIdx.x * blockDim.x + threadIdx.x;
    if (v >= n4) return;
    float4 a = *(const float4*)(x + (size_t)v * 4);
    __nv_bfloat16 h0 = __float2bfloat16(a.x), h1 = __float2bfloat16(a.y);
    __nv_bfloat16 h2 = __float2bfloat16(a.z), h3 = __float2bfloat16(a.w);
    __nv_bfloat16 l0 = __float2bfloat16(a.x - __bfloat162float(h0));
    __nv_bfloat16 l1 = __float2bfloat16(a.y - __bfloat162float(h1));
    __nv_bfloat16 l2 = __float2bfloat16(a.z - __bfloat162float(h2));
    __nv_bfloat16 l3 = __float2bfloat16(a.w - __bfloat162float(h3));
    __nv_bfloat162* ph = (__nv_bfloat162*)(g_xh + (size_t)v * 4);
    __nv_bfloat162* pl = (__nv_bfloat162*)(g_xl + (size_t)v * 4);
    ph[0] = __halves2bfloat162(h0, h1); ph[1] = __halves2bfloat162(h2, h3);
    pl[0] = __halves2bfloat162(l0, l1); pl[1] = __halves2bfloat162(l2, l3);
}
__global__ void k_split_w(const float* __restrict__ wih, const float* __restrict__ whh) {
    int i = blockIdx.x * blockDim.x + threadIdx.x;
    if (i >= G3 * HD) return;
    float v = wih[i];
    __nv_bfloat16 h = __float2bfloat16(v);
    g_wih_h[i] = h;
    g_wih_l[i] = __float2bfloat16(v - __bfloat162float(h));
    float w = whh[i];
    __nv_bfloat16 hh = __float2bfloat16(w);
    g_whh_h[i] = hh;
    g_whh_l[i] = __float2bfloat16(w - __bfloat162float(hh));
}

// ---------------- setup (validated) ----------------
__global__ void k_setup(const int* __restrict__ start, int T) {
    __shared__ int s_cnt[1024];
    int tid = threadIdx.x;
    int per = (T + 1023) / 1024;
    int b0 = tid * per, b1 = min(T, b0 + per);
    int c = 0;
    for (int t = b0; t < b1; t++)
        if (t == 0 || start[t] != 0) c++;
    s_cnt[tid] = c;
    __syncthreads();
    if (tid == 0) {
        int run = 0;
        for (int i = 0; i < 1024; i++) { int v = s_cnt[i]; s_cnt[i] = run; run += v; }
        g_nep = run;
        g_start0 = (start[0] != 0);
    }
    __syncthreads();
    int e = s_cnt[tid];
    for (int t = b0; t < b1; t++)
        if (t == 0 || start[t] != 0) g_starts[e++] = t;
    int nep = g_nep;
    if (tid == 0) g_starts[nep] = T;
    __syncthreads();
    for (int b = tid; b <= T + 1; b += 1024) g_hist[b] = 0;
    __syncthreads();
    for (int e2 = tid; e2 < nep; e2 += 1024) {
        int L = g_starts[e2 + 1] - g_starts[e2];
        g_len[e2] = L;
        atomicAdd(&g_hist[L], 1);
    }
    __syncthreads();
    int NB = T + 2;
    int per2 = (NB + 1023) / 1024;
    int c0 = tid * per2, c1 = min(NB, c0 + per2);
    int s = 0;
    for (int b = c0; b < c1; b++) s += g_hist[b];
    s_cnt[tid] = s;
    __syncthreads();
    if (tid == 0) {
        int run = 0;
        for (int i = 1023; i >= 0; i--) { int v = s_cnt[i]; s_cnt[i] = run; run += v; }
    }
    __syncthreads();
    int run = s_cnt[tid];
    for (int b = c1 - 1; b >= c0; b--) { run += g_hist[b]; g_suffix[b] = run; }
    __syncthreads();
    for (int b = tid; b <= T; b += 1024) g_off[b] = g_suffix[b + 1];
    for (int j = tid; j <= NRA; j += 1024) g_nact[j] = g_suffix[j + 1];
    __syncthreads();
    for (int e2 = tid; e2 < nep; e2 += 1024) {
        int L = g_len[e2];
        int p = atomicAdd(&g_off[L], 1);
        g_sorted[p] = e2;
    }
}

// ---------------- igates GEMM (cp.async pipelined) ----------------
__device__ __forceinline__ void ig_issue(uint32_t sb, int stage, int c,
                                         int m0, int n0, int T, int tid) {
    uint32_t st = sb + stage * IGS_STRIDE;
    int cb = c * 64;
#pragma unroll
    for (int v = tid; v < 1024; v += 256) {
        int r = v >> 3, u = v & 7;
        int row = min(m0 + r, T - 1);
        uint32_t off = (uint32_t)(r * 128 + (((u ^ (r & 7))) << 4));
        size_t src = (size_t)row * HD + cb + u * 8;
        cpa16(st + IGS_AH + off, g_xh + src);
        cpa16(st + IGS_AL + off, g_xl + src);
    }
#pragma unroll
    for (int v = tid; v < 512; v += 256) {
        int r = v >> 3, u = v & 7;
        uint32_t off = (uint32_t)(r * 128 + (((u ^ (r & 7))) << 4));
        size_t src = (size_t)(n0 + r) * HD + cb + u * 8;
        cpa16(st + IGS_BH + off, g_wih_h + src);
        cpa16(st + IGS_BL + off, g_wih_l + src);
    }
    CP_COMMIT();
}
__device__ __forceinline__ void ig_mma3(uint32_t sb, int stage, float (&acc)[2][4][4],
                                        int lane, int wm, int wn) {
    uint32_t st = sb + stage * IGS_STRIDE;
    mma_chunk(st + IGS_AH, st + IGS_BH, acc, lane, wm, wn);
    mma_chunk(st + IGS_AH, st + IGS_BL, acc, lane, wm, wn);
    mma_chunk(st + IGS_AL, st + IGS_BH, acc, lane, wm, wn);
}
__global__ void __launch_bounds__(256) k_ig(const float* __restrict__ bias, int T) {
    extern __shared__ __align__(128) char smem[];
    uint32_t sb = smem_u32(smem);
    int tid = threadIdx.x, lane = tid & 31, wid = tid >> 5;
    int wm = wid >> 1, wn = wid & 1;
    int n0 = blockIdx.x * 64, m0 = blockIdx.y * 128;

    float acc[2][4][4];
#pragma unroll
    for (int a = 0; a < 2; a++)
#pragma unroll
        for (int b = 0; b < 4; b++)
#pragma unroll
            for (int cdx = 0; cdx < 4; cdx++) acc[a][b][cdx] = 0.f;

    ig_issue(sb, 0, 0, m0, n0, T, tid);
    ig_issue(sb, 1, 1, m0, n0, T, tid);

    CP_WAIT(1); __syncthreads();
    ig_mma3(sb, 0, acc, lane, wm, wn);
    __syncthreads();
    ig_issue(sb, 0, 2, m0, n0, T, tid);

    CP_WAIT(1); __syncthreads();
    ig_mma3(sb, 1, acc, lane, wm, wn);
    __syncthreads();
    ig_issue(sb, 1, 3, m0, n0, T, tid);

    CP_WAIT(1); __syncthreads();
    ig_mma3(sb, 0, acc, lane, wm, wn);
    __syncthreads();

    CP_WAIT(0); __syncthreads();
    ig_mma3(sb, 1, acc, lane, wm, wn);

    // epilogue
#pragma unroll
    for (int nt = 0; nt < 4; nt++) {
        int col = n0 + wn * 32 + nt * 8 + (lane & 3) * 2;
        float b0 = bias[col], b1 = bias[col + 1];
#pragma unroll
        for (int mt = 0; mt < 2; mt++) {
            int row = m0 + wm * 32 + mt * 16 + (lane >> 2);
            if (row < T) {
                float* p0 = g_ig + (size_t)row * G3 + col;
                p0[0] = acc[mt][nt][0] + b0;
                p0[1] = acc[mt][nt][1] + b1;
            }
            if (row + 8 < T) {
                float* p1 = g_ig + (size_t)(row + 8) * G3 + col;
                p1[0] = acc[mt][nt][2] + b0;
                p1[1] = acc[mt][nt][3] + b1;
            }
        }
    }
}

// ---------------- round-j GEMM (cp.async pipelined, on-the-fly split) ----------
__device__ __forceinline__ void hg_issue(uint32_t sb, char* smem, int stage, int c,
                                         const float* y, int n0, int tid) {
    uint32_t st = sb + stage * HGS_STRIDE;
    const int* s_t = (const int*)(smem + HG_T);
    int cb = c * 64;
#pragma unroll
    for (int v = tid; v < 2048; v += 256) {
        int r = v >> 4, u = v & 15;
        const float* src = y + (size_t)(s_t[r] - 1) * HD + cb + u * 4;
        cpa16(st + HGS_A32 + r * 256 + u * 16, src);
    }
#pragma unroll
    for (int v = tid; v < 512; v += 256) {
        int r = v >> 3, u = v & 7;
        uint32_t off = (uint32_t)(r * 128 + (((u ^ (r & 7))) << 4));
        size_t src = (size_t)(n0 + r) * HD + cb + u * 8;
        cpa16(st + HGS_BH + off, g_whh_h + src);
        cpa16(st + HGS_BL + off, g_whh_l + src);
    }
    CP_COMMIT();
}
__device__ __forceinline__ void hg_convert(char* smem, int stage, int tid) {
    const float* a32 = (const float*)(smem + stage * HGS_STRIDE + HGS_A32);
#pragma unroll
    for (int v = tid; v < 1024; v += 256) {
        int r = v >> 3, u = v & 7;
        float4 f0 = *(const float4*)(a32 + r * 64 + u * 8);
        float4 f1 = *(const float4*)(a32 + r * 64 + u * 8 + 4);
        float fv[8] = {f0.x, f0.y, f0.z, f0.w, f1.x, f1.y, f1.z, f1.w};
        __nv_bfloat16 hi[8], lo[8];
#pragma unroll
        for (int q = 0; q < 8; q++) {
            hi[q] = __float2bfloat16(fv[q]);
            lo[q] = __float2bfloat16(fv[q] - __bfloat162float(hi[q]));
        }
        uint32_t off = (uint32_t)(r * 128 + (((u ^ (r & 7))) << 4));
        *(uint4*)(smem + HG_CAH + off) = *(const uint4*)hi;
        *(uint4*)(smem + HG_CAL + off) = *(const uint4*)lo;
    }
}
__device__ __forceinline__ void hg_mma3(uint32_t sb, int stage, float (&acc)[2][4][4],
                                        int lane, int wm, int wn) {
    uint32_t bs = sb + stage * HGS_STRIDE;
    mma_chunk(sb + HG_CAH, bs + HGS_BH, acc, lane, wm, wn);
    mma_chunk(sb + HG_CAH, bs + HGS_BL, acc, lane, wm, wn);
    mma_chunk(sb + HG_CAL, bs + HGS_BH, acc, lane, wm, wn);
}
__global__ void __launch_bounds__(256) k_hg(const float* __restrict__ y, int j) {
    extern __shared__ __align__(128) char smem[];
    uint32_t sb = smem_u32(smem);
    int* s_t = (int*)(smem + HG_T);
    int nj = g_nact[j];
    int mt0 = blockIdx.y * 128;
    if (mt0 >= nj) return;
    int tid = threadIdx.x, lane = tid & 31, wid = tid >> 5;
    int wm = wid >> 1, wn = wid & 1;
    int n0 = blockIdx.x * 64;

    if (tid < 128) {
        int m = mt0 + tid;
        s_t[tid] = (m < nj) ? (g_starts[g_sorted[m]] + j) : 1;
    }
    __syncthreads();

    float acc[2][4][4];
#pragma unroll
    for (int a = 0; a < 2; a++)
#pragma unroll
        for (int b = 0; b < 4; b++)
#pragma unroll
            for (int cdx = 0; cdx < 4; cdx++) acc[a][b][cdx] = 0.f;

    hg_issue(sb, smem, 0, 0, y, n0, tid);
    hg_issue(sb, smem, 1, 1, y, n0, tid);

    CP_WAIT(1); __syncthreads();
    hg_convert(smem, 0, tid); __syncthreads();
    hg_mma3(sb, 0, acc, lane, wm, wn);
    __syncthreads();
    hg_issue(sb, smem, 0, 2, y, n0, tid);

    CP_WAIT(1); __syncthreads();
    hg_convert(smem, 1, tid); __syncthreads();
    hg_mma3(sb, 1, acc, lane, wm, wn);
    __syncthreads();
    hg_issue(sb, smem, 1, 3, y, n0, tid);

    CP_WAIT(1); __syncthreads();
    hg_convert(smem, 0, tid); __syncthreads();
    hg_mma3(sb, 0, acc, lane, wm, wn);
    __syncthreads();

    CP_WAIT(0); __syncthreads();
    hg_convert(smem, 1, tid); __syncthreads();
    hg_mma3(sb, 1, acc, lane, wm, wn);

#pragma unroll
    for (int nt = 0; nt < 4; nt++) {
        int col = n0 + wn * 32 + nt * 8 + (lane & 3) * 2;
#pragma unroll
        for (int mt = 0; mt < 2; mt++) {
            int m = mt0 + wm * 32 + mt * 16 + (lane >> 2);
            if (m < nj) {
                float* p = g_hg + (size_t)m * G3 + col;
                p[0] = acc[mt][nt][0]; p[1] = acc[mt][nt][1];
            }
            if (m + 8 < nj) {
                float* p = g_hg + (size_t)(m + 8) * G3 + col;
                p[0] = acc[mt][nt][2]; p[1] = acc[mt][nt][3];
            }
        }
    }
}

// ---------------- gates for round 0 ----------------
__global__ void __launch_bounds__(256) k_gates0(float* __restrict__ y,
                                                const float* __restrict__ state,
                                                const float* __restrict__ Whh,
                                                const float* __restrict__ bias_n) {
    int nj = g_nact[0];
    __shared__ float sh[HD];
    int i = threadIdx.x;
    for (int m = blockIdx.x; m < nj; m += gridDim.x) {
        int e = g_sorted[m];
        int t = g_starts[e];
        const float* ig = g_ig + (size_t)t * G3;
        float o;
        if (e == 0 && !g_start0) {
            sh[i] = state[i];
            __syncthreads();
            float sr = 0.f, sz = 0.f, sn = 0.f;
            const float4* h4 = (const float4*)sh;
            const float4* w0 = (const float4*)(Whh + (size_t)i * HD);
            const float4* w1 = (const float4*)(Whh + (size_t)(HD + i) * HD);
            const float4* w2 = (const float4*)(Whh + (size_t)(2 * HD + i) * HD);
#pragma unroll 8
            for (int k = 0; k < 64; k++) {
                float4 hv = h4[k];
                float4 a = w0[k], b = w1[k], cc = w2[k];
                sr = fmaf(hv.x, a.x, sr);  sr = fmaf(hv.y, a.y, sr);
                sr = fmaf(hv.z, a.z, sr);  sr = fmaf(hv.w, a.w, sr);
                sz = fmaf(hv.x, b.x, sz);  sz = fmaf(hv.y, b.y, sz);
                sz = fmaf(hv.z, b.z, sz);  sz = fmaf(hv.w, b.w, sz);
                sn = fmaf(hv.x, cc.x, sn); sn = fmaf(hv.y, cc.y, sn);
                sn = fmaf(hv.z, cc.z, sn); sn = fmaf(hv.w, cc.w, sn);
            }
            float h = sh[i];
            float r = sigm(ig[i] + sr);
            float z = sigm(ig[HD + i] + sz);
            float n = tanhs(ig[2 * HD + i] + r * (sn + bias_n[i]));
            o = n + z * (h - n);
            __syncthreads();
        } else {
            float r = sigm(ig[i]);
            float z = sigm(ig[HD + i]);
            float n = tanhs(ig[2 * HD + i] + r * bias_n[i]);
            o = n * (1.f - z);
        }
        y[(size_t)t * HD + i] = o;
    }
}

// ---------------- gates for round j>=1 ----------------
__global__ void __launch_bounds__(256) k_gates(float* __restrict__ y,
                                               const float* __restrict__ bias_n, int j) {
    int nj = g_nact[j];
    int m = blockIdx.x;
    if (m >= nj) return;
    int i = threadIdx.x;
    int t = g_starts[g_sorted[m]] + j;
    const float* ig = g_ig + (size_t)t * G3;
    const float* hg = g_hg + (size_t)m * G3;
    float h = y[(size_t)(t - 1) * HD + i];
    float r = sigm(ig[i] + hg[i]);
    float z = sigm(ig[HD + i] + hg[HD + i]);
    float n = tanhs(ig[2 * HD + i] + r * (hg[2 * HD + i] + bias_n[i]));
    y[(size_t)t * HD + i] = n + z * (h - n);
}

// ---------------- finisher: episodes with len > RNDJ ----------------
__global__ void __launch_bounds__(256) k_finish(const float* __restrict__ Whh,
                                                const float* __restrict__ bias_n,
                                                float* y) {
    int nover = g_nact[RNDJ];
    __shared__ __align__(16) float h[HD];
    int i = threadIdx.x;
    const float4* w0 = (const float4*)(Whh + (size_t)i * HD);
    const float4* w1 = (const float4*)(Whh + (size_t)(HD + i) * HD);
    const float4* w2 = (const float4*)(Whh + (size_t)(2 * HD + i) * HD);
    float bn = bias_n[i];
    for (int idx = blockIdx.x; idx < nover; idx += gridDim.x) {
        int e = g_sorted[idx];
        int ts = g_starts[e], L = g_len[e];
        for (int j = RNDJ; j < L; j++) {
            int t = ts + j;
            h[i] = y[(size_t)(t - 1) * HD + i];
            __syncthreads();
            const float4* h4 = (const float4*)h;
            float sr = 0.f, sz = 0.f, sn = 0.f;
#pragma unroll 8
            for (int k = 0; k < 64; k++) {
                float4 hv = h4[k];
                float4 a = w0[k], b = w1[k], cc = w2[k];
                sr = fmaf(hv.x, a.x, sr);  sr = fmaf(hv.y, a.y, sr);
                sr = fmaf(hv.z, a.z, sr);  sr = fmaf(hv.w, a.w, sr);
                sz = fmaf(hv.x, b.x, sz);  sz = fmaf(hv.y, b.y, sz);
                sz = fmaf(hv.z, b.z, sz);  sz = fmaf(hv.w, b.w, sz);
                sn = fmaf(hv.x, cc.x, sn); sn = fmaf(hv.y, cc.y, sn);
                sn = fmaf(hv.z, cc.z, sn); sn = fmaf(hv.w, cc.w, sn);
            }
            const float* ig = g_ig + (size_t)t * G3;
            float r = sigm(ig[i] + sr);
            float z = sigm(ig[HD + i] + sz);
            float n = tanhs(ig[2 * HD + i] + r * (sn + bn));
            float o = n + z * (h[i] - n);
            __syncthreads();
            y[(size_t)t * HD + i] = o;
        }
        __syncthreads();
    }
}

// ---------------- tail: final_state = y[T-1] ----------------
__global__ void k_tail(float* out, int T, long long out_size) {
    long long base = (long long)T * HD;
    if (out_size >= base + HD) {
        int i = threadIdx.x;
        out[base + i] = out[base - HD + i];
    }
}

// ---------------- launch ----------------
extern "C" void kernel_launch(void* const* d_in, const int* in_sizes, int n_in,
                              void* d_out, int out_size) {
    const float* x      = (const float*)d_in[0];
    const float* state  = (const float*)d_in[1];
    const int*   start  = (const int*)d_in[2];
    const float* Wih    = (const float*)d_in[4];
    const float* Whh    = (const float*)d_in[5];
    const float* bias   = (const float*)d_in[6];
    const float* bias_n = (const float*)d_in[7];
    float* out = (float*)d_out;

    int T = in_sizes[2];
    if (T > MAXT) T = MAXT;

    cudaFuncSetAttribute(k_ig, cudaFuncAttributeMaxDynamicSharedMemorySize, IG_SMEM);
    cudaFuncSetAttribute(k_hg, cudaFuncAttributeMaxDynamicSharedMemorySize, HG_SMEM);

    int n4 = T * HD / 4;
    k_split_x<<<(n4 + 255) / 256, 256>>>(x, n4);
    k_split_w<<<(G3 * HD + 255) / 256, 256>>>(Wih, Whh);
    k_setup<<<1, 1024>>>(start, T);
    k_ig<<<dim3(12, (T + 127) / 128), 256, IG_SMEM>>>(bias, T);
    k_gates0<<<2048, 256>>>(out, state, Whh, bias_n);
    for (int j = 1; j < RNDJ; j++) {
        int maxnj = T / (j + 1) + 1;
        k_hg<<<dim3(12, (maxnj + 127) / 128), 256, HG_SMEM>>>(out, j);
        k_gates<<<maxnj, 256>>>(out, bias_n, j);
    }
    k_finish<<<512, 256>>>(Whh, bias_n, out);
    k_tail<<<1, 256>>>(out, T, (long long)out_size);
}

// round 5
// speedup vs baseline: 1.7842x; 1.0422x over previous
#include <cuda_runtime.h>
#include <cuda_bf16.h>
#include <cstdint>
#include <math.h>

#define MAXT 65536
#define HD   256
#define G3   768
#define NRA  40
#define RNDJ 6        // rounds 0..5 batched; finisher handles j>=6

// ---------------- device scratch ----------------
__device__ float g_ig[(size_t)MAXT * G3];
__device__ __align__(16) __nv_bfloat16 g_xh[(size_t)MAXT * HD];
__device__ __align__(16) __nv_bfloat16 g_xl[(size_t)MAXT * HD];
__device__ __align__(16) __nv_bfloat16 g_wih_h[G3 * HD];
__device__ __align__(16) __nv_bfloat16 g_wih_l[G3 * HD];
__device__ __align__(16) __nv_bfloat16 g_wq_h[G3 * HD];   // Whh gate-interleaved split
__device__ __align__(16) __nv_bfloat16 g_wq_l[G3 * HD];
__device__ int g_starts[MAXT + 1];
__device__ int g_len[MAXT];
__device__ int g_sorted[MAXT];
__device__ int g_hist[MAXT + 2];
__device__ int g_suffix[MAXT + 2];
__device__ int g_off[MAXT + 2];
__device__ int g_nact[NRA + 2];
__device__ int g_nep;
__device__ int g_start0;

// ---------------- math helpers ----------------
__device__ __forceinline__ float sigm(float x) {
    x = fminf(15.f, fmaxf(-15.f, x));
    return 1.f / (1.f + __expf(-x));
}
__device__ __forceinline__ float tanhs(float x) {
    x = fminf(9.f, fmaxf(-9.f, x));
    float e = __expf(-2.f * x);
    return (1.f - e) / (1.f + e);
}
__device__ __forceinline__ uint32_t smem_u32(const void* p) {
    uint32_t a;
    asm("{ .reg .u64 t; cvta.to.shared.u64 t, %1; cvt.u32.u64 %0, t; }" : "=r"(a) : "l"(p));
    return a;
}
__device__ __forceinline__ void cpa16(uint32_t s, const void* g) {
    asm volatile("cp.async.cg.shared.global [%0], [%1], 16;"
                 :: "r"(s), "l"(g) : "memory");
}
#define CP_COMMIT() asm volatile("cp.async.commit_group;" ::: "memory")
#define CP_WAIT(n)  asm volatile("cp.async.wait_group %0;" :: "n"(n) : "memory")

__device__ __forceinline__ void ldsm4(uint32_t a, uint32_t* r) {
    asm volatile("ldmatrix.sync.aligned.m8n8.x4.shared.b16 {%0,%1,%2,%3}, [%4];"
                 : "=r"(r[0]), "=r"(r[1]), "=r"(r[2]), "=r"(r[3]) : "r"(a));
}
__device__ __forceinline__ void mma16816(float* c, const uint32_t* a,
                                         uint32_t b0, uint32_t b1) {
    asm volatile("mma.sync.aligned.m16n8k16.row.col.f32.bf16.bf16.f32 "
                 "{%0,%1,%2,%3}, {%4,%5,%6,%7}, {%8,%9}, {%0,%1,%2,%3};"
                 : "+f"(c[0]), "+f"(c[1]), "+f"(c[2]), "+f"(c[3])
                 : "r"(a[0]), "r"(a[1]), "r"(a[2]), "r"(a[3]), "r"(b0), "r"(b1));
}

// Fused 3-term chunk MMA. NG = number of 32-col B groups per warp.
// Layout: rows*128B, swizzle off = r*128 + ((u ^ (r&7))<<4), u = 16B unit.
template<int NG>
__device__ __forceinline__ void mma_fused(uint32_t ah, uint32_t al,
                                          uint32_t bh, uint32_t bl,
                                          float (&acc)[2][4 * NG][4],
                                          int lane, int wm, int wn) {
    int arow = wm * 32 + (lane & 7) + (((lane >> 3) & 1) << 3);
    int aks  = (lane >> 4) & 1;
    int axor = arow & 7;
    uint32_t ahB = ah + arow * 128, alB = al + arow * 128;
    int brow0 = (lane & 7) + (((lane >> 4) & 1) << 3);
    int bks  = (lane >> 3) & 1;
#pragma unroll
    for (int ks = 0; ks < 4; ks++) {
        uint32_t au = (uint32_t)(((2 * ks + aks) ^ axor) << 4);
        uint32_t AH0[4], AH1[4], AL0[4], AL1[4];
        ldsm4(ahB + au,        AH0);
        ldsm4(ahB + 2048 + au, AH1);
        ldsm4(alB + au,        AL0);
        ldsm4(alB + 2048 + au, AL1);
#pragma unroll
        for (int g = 0; g < NG; g++) {
            int brow = wn * (32 * NG) + g * 32 + brow0;
            int bxor = brow & 7;
            uint32_t bu = (uint32_t)(((2 * ks + bks) ^ bxor) << 4);
            uint32_t bb = (uint32_t)(brow * 128);
            uint32_t BH0[4], BH1[4], BL0[4], BL1[4];
            ldsm4(bh + bb + bu,        BH0);
            ldsm4(bh + bb + 2048 + bu, BH1);
            ldsm4(bl + bb + bu,        BL0);
            ldsm4(bl + bb + 2048 + bu, BL1);
            int nb = g * 4;
            // hi*hi
            mma16816(acc[0][nb+0], AH0, BH0[0], BH0[1]);
            mma16816(acc[0][nb+1], AH0, BH0[2], BH0[3]);
            mma16816(acc[0][nb+2], AH0, BH1[0], BH1[1]);
            mma16816(acc[0][nb+3], AH0, BH1[2], BH1[3]);
            mma16816(acc[1][nb+0], AH1, BH0[0], BH0[1]);
            mma16816(acc[1][nb+1], AH1, BH0[2], BH0[3]);
            mma16816(acc[1][nb+2], AH1, BH1[0], BH1[1]);
            mma16816(acc[1][nb+3], AH1, BH1[2], BH1[3]);
            // hi*lo
            mma16816(acc[0][nb+0], AH0, BL0[0], BL0[1]);
            mma16816(acc[0][nb+1], AH0, BL0[2], BL0[3]);
            mma16816(acc[0][nb+2], AH0, BL1[0], BL1[1]);
            mma16816(acc[0][nb+3], AH0, BL1[2], BL1[3]);
            mma16816(acc[1][nb+0], AH1, BL0[0], BL0[1]);
            mma16816(acc[1][nb+1], AH1, BL0[2], BL0[3]);
            mma16816(acc[1][nb+2], AH1, BL1[0], BL1[1]);
            mma16816(acc[1][nb+3], AH1, BL1[2], BL1[3]);
            // lo*hi
            mma16816(acc[0][nb+0], AL0, BH0[0], BH0[1]);
            mma16816(acc[0][nb+1], AL0, BH0[2], BH0[3]);
            mma16816(acc[0][nb+2], AL0, BH1[0], BH1[1]);
            mma16816(acc[0][nb+3], AL0, BH1[2], BH1[3]);
            mma16816(acc[1][nb+0], AL1, BH0[0], BH0[1]);
            mma16816(acc[1][nb+1], AL1, BH0[2], BH0[3]);
            mma16816(acc[1][nb+2], AL1, BH1[0], BH1[1]);
            mma16816(acc[1][nb+3], AL1, BH1[2], BH1[3]);
        }
    }
}

// ---------------- k_ig stage layout: 3 stages x 48KB ----------------
#define IGS_AH 0
#define IGS_AL 16384
#define IGS_BH 32768
#define IGS_BL 40960
#define IGS_STRIDE 49152
#define IG_SMEM (3 * IGS_STRIDE)

// ---------------- k_hg2: 2 stages (A32 32KB + BH 24KB + BL 24KB) + conv + s_t --
#define HG2_A32 0
#define HG2_BH  32768
#define HG2_BL  57344
#define HG2_STRIDE 81920
#define HG2_CAH 163840
#define HG2_CAL 180224
#define HG2_T   196608
#define HG2_SMEM 197120
#define CSTRIDE 196

// ---------------- split kernels ----------------
__global__ void k_split_x(const float* __restrict__ x, int n4) {
    int v = blockIdx.x * blockDim.x + threadIdx.x;
    if (v >= n4) return;
    float4 a = *(const float4*)(x + (size_t)v * 4);
    __nv_bfloat16 h0 = __float2bfloat16(a.x), h1 = __float2bfloat16(a.y);
    __nv_bfloat16 h2 = __float2bfloat16(a.z), h3 = __float2bfloat16(a.w);
    __nv_bfloat16 l0 = __float2bfloat16(a.x - __bfloat162float(h0));
    __nv_bfloat16 l1 = __float2bfloat16(a.y - __bfloat162float(h1));
    __nv_bfloat16 l2 = __float2bfloat16(a.z - __bfloat162float(h2));
    __nv_bfloat16 l3 = __float2bfloat16(a.w - __bfloat162float(h3));
    __nv_bfloat162* ph = (__nv_bfloat162*)(g_xh + (size_t)v * 4);
    __nv_bfloat162* pl = (__nv_bfloat162*)(g_xl + (size_t)v * 4);
    ph[0] = __halves2bfloat162(h0, h1); ph[1] = __halves2bfloat162(h2, h3);
    pl[0] = __halves2bfloat162(l0, l1); pl[1] = __halves2bfloat162(l2, l3);
}
__global__ void k_split_w(const float* __restrict__ wih, const float* __restrict__ whh) {
    int i = blockIdx.x * blockDim.x + threadIdx.x;
    if (i >= G3 * HD) return;
    float v = wih[i];
    __nv_bfloat16 h = __float2bfloat16(v);
    g_wih_h[i] = h;
    g_wih_l[i] = __float2bfloat16(v - __bfloat162float(h));
    // gate-interleaved Whh: out row q -> nt=q/192, rem=q%192, g=rem/64, il=rem%64
    int q = i >> 8, k = i & 255;
    int nt = q / 192, rem = q % 192;
    int gg = rem >> 6, il = rem & 63;
    float w = whh[(size_t)(gg * 256 + nt * 64 + il) * HD + k];
    __nv_bfloat16 hh = __float2bfloat16(w);
    g_wq_h[i] = hh;
    g_wq_l[i] = __float2bfloat16(w - __bfloat162float(hh));
}

// ---------------- setup with shfl scans ----------------
__device__ __forceinline__ int warp_scan_incl(int v, int lane) {
#pragma unroll
    for (int o = 1; o < 32; o <<= 1) {
        int n = __shfl_up_sync(0xFFFFFFFFu, v, o);
        if (lane >= o) v += n;
    }
    return v;
}
__global__ void k_setup(const int* __restrict__ start, int T) {
    __shared__ int s_w[32];
    int tid = threadIdx.x, lane = tid & 31, w = tid >> 5;
    int per = (T + 1023) / 1024;
    int b0 = tid * per, b1 = min(T, b0 + per);

    int c = 0;
    for (int t = b0; t < b1; t++)
        if (t == 0 || start[t] != 0) c++;
    int inc = warp_scan_incl(c, lane);
    if (lane == 31) s_w[w] = inc;
    __syncthreads();
    if (w == 0) s_w[lane] = warp_scan_incl(s_w[lane], lane);
    __syncthreads();
    int excl = inc - c + (w ? s_w[w - 1] : 0);
    int nep = s_w[31];
    if (tid == 0) { g_nep = nep; g_start0 = (start[0] != 0); }

    int e = excl;
    for (int t = b0; t < b1; t++)
        if (t == 0 || start[t] != 0) g_starts[e++] = t;
    if (tid == 0) g_starts[nep] = T;
    __syncthreads();

    for (int b = tid; b <= T + 1; b += 1024) g_hist[b] = 0;
    __syncthreads();
    for (int e2 = tid; e2 < nep; e2 += 1024) {
        int L = g_starts[e2 + 1] - g_starts[e2];
        g_len[e2] = L;
        atomicAdd(&g_hist[L], 1);
    }
    __syncthreads();

    int NB = T + 2;
    int per2 = (NB + 1023) / 1024;
    int c0 = tid * per2, c1 = min(NB, c0 + per2);
    int s = 0;
    for (int b = c0; b < c1; b++) s += g_hist[b];
    int inc2 = warp_scan_incl(s, lane);
    if (lane == 31) s_w[w] = inc2;
    __syncthreads();
    if (w == 0) s_w[lane] = warp_scan_incl(s_w[lane], lane);
    __syncthreads();
    int incl_full = inc2 + (w ? s_w[w - 1] : 0);
    int total2 = s_w[31];
    int run = total2 - incl_full;
    for (int b = c1 - 1; b >= c0; b--) { run += g_hist[b]; g_suffix[b] = run; }
    __syncthreads();

    for (int b = tid; b <= T; b += 1024) g_off[b] = g_suffix[b + 1];
    for (int j = tid; j <= NRA; j += 1024) g_nact[j] = g_suffix[j + 1];
    __syncthreads();
    for (int e2 = tid; e2 < nep; e2 += 1024) {
        int L = g_len[e2];
        int p = atomicAdd(&g_off[L], 1);
        g_sorted[p] = e2;
    }
}

// ---------------- igates GEMM (3-stage cp.async + fused 3-term) ----------------
__device__ __forceinline__ void ig_issue(uint32_t sb, int stage, int c,
                                         int m0, int n0, int T, int tid) {
    uint32_t st = sb + stage * IGS_STRIDE;
    int cb = c * 64;
#pragma unroll
    for (int v = tid; v < 1024; v += 256) {
        int r = v >> 3, u = v & 7;
        int row = min(m0 + r, T - 1);
        uint32_t off = (uint32_t)(r * 128 + (((u ^ (r & 7))) << 4));
        size_t src = (size_t)row * HD + cb + u * 8;
        cpa16(st + IGS_AH + off, g_xh + src);
        cpa16(st + IGS_AL + off, g_xl + src);
    }
#pragma unroll
    for (int v = tid; v < 512; v += 256) {
        int r = v >> 3, u = v & 7;
        uint32_t off = (uint32_t)(r * 128 + (((u ^ (r & 7))) << 4));
        size_t src = (size_t)(n0 + r) * HD + cb + u * 8;
        cpa16(st + IGS_BH + off, g_wih_h + src);
        cpa16(st + IGS_BL + off, g_wih_l + src);
    }
    CP_COMMIT();
}
__global__ void __launch_bounds__(256) k_ig(const float* __restrict__ bias, int T) {
    extern __shared__ __align__(128) char smem[];
    uint32_t sb = smem_u32(smem);
    int tid = threadIdx.x, lane = tid & 31, wid = tid >> 5;
    int wm = wid >> 1, wn = wid & 1;
    int n0 = blockIdx.x * 64, m0 = blockIdx.y * 128;

    float acc[2][4][4];
#pragma unroll
    for (int a = 0; a < 2; a++)
#pragma unroll
        for (int b = 0; b < 4; b++)
#pragma unroll
            for (int cdx = 0; cdx < 4; cdx++) acc[a][b][cdx] = 0.f;

    ig_issue(sb, 0, 0, m0, n0, T, tid);
    ig_issue(sb, 1, 1, m0, n0, T, tid);
    ig_issue(sb, 2, 2, m0, n0, T, tid);

    CP_WAIT(2); __syncthreads();
    {
        uint32_t st = sb + 0 * IGS_STRIDE;
        mma_fused<1>(st + IGS_AH, st + IGS_AL, st + IGS_BH, st + IGS_BL, acc, lane, wm, wn);
    }
    __syncthreads();
    ig_issue(sb, 0, 3, m0, n0, T, tid);

    CP_WAIT(2); __syncthreads();
    {
        uint32_t st = sb + 1 * IGS_STRIDE;
        mma_fused<1>(st + IGS_AH, st + IGS_AL, st + IGS_BH, st + IGS_BL, acc, lane, wm, wn);
    }
    CP_WAIT(1); __syncthreads();
    {
        uint32_t st = sb + 2 * IGS_STRIDE;
        mma_fused<1>(st + IGS_AH, st + IGS_AL, st + IGS_BH, st + IGS_BL, acc, lane, wm, wn);
    }
    CP_WAIT(0); __syncthreads();
    {
        uint32_t st = sb + 0 * IGS_STRIDE;
        mma_fused<1>(st + IGS_AH, st + IGS_AL, st + IGS_BH, st + IGS_BL, acc, lane, wm, wn);
    }

#pragma unroll
    for (int nt = 0; nt < 4; nt++) {
        int col = n0 + wn * 32 + nt * 8 + (lane & 3) * 2;
        float b0 = bias[col], b1 = bias[col + 1];
#pragma unroll
        for (int mt = 0; mt < 2; mt++) {
            int row = m0 + wm * 32 + mt * 16 + (lane >> 2);
            if (row < T) {
                float* p0 = g_ig + (size_t)row * G3 + col;
                p0[0] = acc[mt][nt][0] + b0;
                p0[1] = acc[mt][nt][1] + b1;
            }
            if (row + 8 < T) {
                float* p1 = g_ig + (size_t)(row + 8) * G3 + col;
                p1[0] = acc[mt][nt][2] + b0;
                p1[1] = acc[mt][nt][3] + b1;
            }
        }
    }
}

// ---------------- fused round kernel: GEMM 128x192 + gate epilogue -> y ----------
__device__ __forceinline__ void hg2_issue(uint32_t sb, char* smem, int stage, int c,
                                          const float* y, int nt, int tid) {
    uint32_t st = sb + stage * HG2_STRIDE;
    const int* s_t = (const int*)(smem + HG2_T);
    int cb = c * 64;
#pragma unroll
    for (int v = tid; v < 2048; v += 256) {
        int r = v >> 4, u = v & 15;
        const float* src = y + (size_t)(s_t[r] - 1) * HD + cb + u * 4;
        cpa16(st + HG2_A32 + r * 256 + u * 16, src);
    }
#pragma unroll
    for (int v = tid; v < 1536; v += 256) {
        int r = v >> 3, u = v & 7;
        uint32_t off = (uint32_t)(r * 128 + (((u ^ (r & 7))) << 4));
        size_t src = (size_t)(nt * 192 + r) * HD + cb + u * 8;
        cpa16(st + HG2_BH + off, g_wq_h + src);
        cpa16(st + HG2_BL + off, g_wq_l + src);
    }
    CP_COMMIT();
}
__device__ __forceinline__ void hg2_convert(char* smem, int stage, int tid) {
    const float* a32 = (const float*)(smem + stage * HG2_STRIDE + HG2_A32);
#pragma unroll
    for (int v = tid; v < 1024; v += 256) {
        int r = v >> 3, u = v & 7;
        float4 f0 = *(const float4*)(a32 + r * 64 + u * 8);
        float4 f1 = *(const float4*)(a32 + r * 64 + u * 8 + 4);
        float fv[8] = {f0.x, f0.y, f0.z, f0.w, f1.x, f1.y, f1.z, f1.w};
        __nv_bfloat16 hi[8], lo[8];
#pragma unroll
        for (int q = 0; q < 8; q++) {
            hi[q] = __float2bfloat16(fv[q]);
            lo[q] = __float2bfloat16(fv[q] - __bfloat162float(hi[q]));
        }
        uint32_t off = (uint32_t)(r * 128 + (((u ^ (r & 7))) << 4));
        *(uint4*)(smem + HG2_CAH + off) = *(const uint4*)hi;
        *(uint4*)(smem + HG2_CAL + off) = *(const uint4*)lo;
    }
}
__global__ void __launch_bounds__(256) k_hg2(float* __restrict__ y,
                                             const float* __restrict__ bias_n, int j) {
    extern __shared__ __align__(128) char smem[];
    uint32_t sb = smem_u32(smem);
    int* s_t = (int*)(smem + HG2_T);
    int nj = g_nact[j];
    int mt0 = blockIdx.y * 128;
    if (mt0 >= nj) return;
    int tid = threadIdx.x, lane = tid & 31, wid = tid >> 5;
    int wm = wid >> 1, wn = wid & 1;
    int nt = blockIdx.x;   // unit block: units [nt*64, nt*64+64)

    if (tid < 128) {
        int m = mt0 + tid;
        s_t[tid] = (m < nj) ? (g_starts[g_sorted[m]] + j) : 1;
    }
    __syncthreads();

    float acc[2][12][4];
#pragma unroll
    for (int a = 0; a < 2; a++)
#pragma unroll
        for (int b = 0; b < 12; b++)
#pragma unroll
            for (int cdx = 0; cdx < 4; cdx++) acc[a][b][cdx] = 0.f;

    hg2_issue(sb, smem, 0, 0, y, nt, tid);
    hg2_issue(sb, smem, 1, 1, y, nt, tid);

    CP_WAIT(1); __syncthreads();
    hg2_convert(smem, 0, tid); __syncthreads();
    mma_fused<3>(sb + HG2_CAH, sb + HG2_CAL,
                 sb + 0 * HG2_STRIDE + HG2_BH, sb + 0 * HG2_STRIDE + HG2_BL,
                 acc, lane, wm, wn);
    __syncthreads();
    hg2_issue(sb, smem, 0, 2, y, nt, tid);

    CP_WAIT(1); __syncthreads();
    hg2_convert(smem, 1, tid); __syncthreads();
    mma_fused<3>(sb + HG2_CAH, sb + HG2_CAL,
                 sb + 1 * HG2_STRIDE + HG2_BH, sb + 1 * HG2_STRIDE + HG2_BL,
                 acc, lane, wm, wn);
    __syncthreads();
    hg2_issue(sb, smem, 1, 3, y, nt, tid);

    CP_WAIT(1); __syncthreads();
    hg2_convert(smem, 0, tid); __syncthreads();
    mma_fused<3>(sb + HG2_CAH, sb + HG2_CAL,
                 sb + 0 * HG2_STRIDE + HG2_BH, sb + 0 * HG2_STRIDE + HG2_BL,
                 acc, lane, wm, wn);

    CP_WAIT(0); __syncthreads();
    hg2_convert(smem, 1, tid); __syncthreads();
    mma_fused<3>(sb + HG2_CAH, sb + HG2_CAL,
                 sb + 1 * HG2_STRIDE + HG2_BH, sb + 1 * HG2_STRIDE + HG2_BL,
                 acc, lane, wm, wn);
    __syncthreads();

    // stage C (pre-activations) into smem [128][CSTRIDE]
    float* C = (float*)smem;
#pragma unroll
    for (int ntv = 0; ntv < 12; ntv++) {
        int g = ntv >> 2, ntl = ntv & 3;
        int col = wn * 96 + g * 32 + ntl * 8 + (lane & 3) * 2;
#pragma unroll
        for (int mt = 0; mt < 2; mt++) {
            int row = wm * 32 + mt * 16 + (lane >> 2);
            C[row * CSTRIDE + col]           = acc[mt][ntv][0];
            C[row * CSTRIDE + col + 1]       = acc[mt][ntv][1];
            C[(row + 8) * CSTRIDE + col]     = acc[mt][ntv][2];
            C[(row + 8) * CSTRIDE + col + 1] = acc[mt][ntv][3];
        }
    }
    __syncthreads();

    // gate epilogue: 128 rows x 64 units (float4 over units)
#pragma unroll 1
    for (int idx = tid; idx < 2048; idx += 256) {
        int row = idx >> 4, q4 = idx & 15;
        if (mt0 + row >= nj) continue;
        int t = s_t[row];
        int i = nt * 64 + q4 * 4;
        const float* cr = C + row * CSTRIDE + q4 * 4;
        float4 rp = *(const float4*)(cr);
        float4 zp = *(const float4*)(cr + 64);
        float4 np = *(const float4*)(cr + 128);
        const float* igrow = g_ig + (size_t)t * G3;
        float4 igr = *(const float4*)(igrow + i);
        float4 igz = *(const float4*)(igrow + HD + i);
        float4 ign = *(const float4*)(igrow + 2 * HD + i);
        float4 h4  = *(const float4*)(y + (size_t)(t - 1) * HD + i);
        float4 bn4 = *(const float4*)(bias_n + i);
        float rv[4] = {rp.x, rp.y, rp.z, rp.w};
        float zv[4] = {zp.x, zp.y, zp.z, zp.w};
        float nv[4] = {np.x, np.y, np.z, np.w};
        float ir[4] = {igr.x, igr.y, igr.z, igr.w};
        float iz[4] = {igz.x, igz.y, igz.z, igz.w};
        float in_[4] = {ign.x, ign.y, ign.z, ign.w};
        float hv[4] = {h4.x, h4.y, h4.z, h4.w};
        float bv[4] = {bn4.x, bn4.y, bn4.z, bn4.w};
        float o[4];
#pragma unroll
        for (int u = 0; u < 4; u++) {
            float r = sigm(ir[u] + rv[u]);
            float z = sigm(iz[u] + zv[u]);
            float n = tanhs(in_[u] + r * (nv[u] + bv[u]));
            o[u] = n + z * (hv[u] - n);
        }
        *(float4*)(y + (size_t)t * HD + i) = make_float4(o[0], o[1], o[2], o[3]);
    }
}

// ---------------- gates for round 0 ----------------
__global__ void __launch_bounds__(256) k_gates0(float* __restrict__ y,
                                                const float* __restrict__ state,
                                                const float* __restrict__ Whh,
                                                const float* __restrict__ bias_n) {
    int nj = g_nact[0];
    __shared__ float sh[HD];
    int i = threadIdx.x;
    for (int m = blockIdx.x; m < nj; m += gridDim.x) {
        int e = g_sorted[m];
        int t = g_starts[e];
        const float* ig = g_ig + (size_t)t * G3;
        float o;
        if (e == 0 && !g_start0) {
            sh[i] = state[i];
            __syncthreads();
            float sr = 0.f, sz = 0.f, sn = 0.f;
            const float4* h4 = (const float4*)sh;
            const float4* w0 = (const float4*)(Whh + (size_t)i * HD);
            const float4* w1 = (const float4*)(Whh + (size_t)(HD + i) * HD);
            const float4* w2 = (const float4*)(Whh + (size_t)(2 * HD + i) * HD);
#pragma unroll 8
            for (int k = 0; k < 64; k++) {
                float4 hv = h4[k];
                float4 a = w0[k], b = w1[k], cc = w2[k];
                sr = fmaf(hv.x, a.x, sr);  sr = fmaf(hv.y, a.y, sr);
                sr = fmaf(hv.z, a.z, sr);  sr = fmaf(hv.w, a.w, sr);
                sz = fmaf(hv.x, b.x, sz);  sz = fmaf(hv.y, b.y, sz);
                sz = fmaf(hv.z, b.z, sz);  sz = fmaf(hv.w, b.w, sz);
                sn = fmaf(hv.x, cc.x, sn); sn = fmaf(hv.y, cc.y, sn);
                sn = fmaf(hv.z, cc.z, sn); sn = fmaf(hv.w, cc.w, sn);
            }
            float h = sh[i];
            float r = sigm(ig[i] + sr);
            float z = sigm(ig[HD + i] + sz);
            float n = tanhs(ig[2 * HD + i] + r * (sn + bias_n[i]));
            o = n + z * (h - n);
            __syncthreads();
        } else {
            float r = sigm(ig[i]);
            float z = sigm(ig[HD + i]);
            float n = tanhs(ig[2 * HD + i] + r * bias_n[i]);
            o = n * (1.f - z);
        }
        y[(size_t)t * HD + i] = o;
    }
}

// ---------------- finisher: episodes with len > RNDJ ----------------
__global__ void __launch_bounds__(256) k_finish(const float* __restrict__ Whh,
                                                const float* __restrict__ bias_n,
                                                float* y) {
    int nover = g_nact[RNDJ];
    __shared__ __align__(16) float h[HD];
    int i = threadIdx.x;
    const float4* w0 = (const float4*)(Whh + (size_t)i * HD);
    const float4* w1 = (const float4*)(Whh + (size_t)(HD + i) * HD);
    const float4* w2 = (const float4*)(Whh + (size_t)(2 * HD + i) * HD);
    float bn = bias_n[i];
    for (int idx = blockIdx.x; idx < nover; idx += gridDim.x) {
        int e = g_sorted[idx];
        int ts = g_starts[e], L = g_len[e];
        for (int j = RNDJ; j < L; j++) {
            int t = ts + j;
            h[i] = y[(size_t)(t - 1) * HD + i];
            __syncthreads();
            const float4* h4 = (const float4*)h;
            float sr = 0.f, sz = 0.f, sn = 0.f;
#pragma unroll 8
            for (int k = 0; k < 64; k++) {
                float4 hv = h4[k];
                float4 a = w0[k], b = w1[k], cc = w2[k];
                sr = fmaf(hv.x, a.x, sr);  sr = fmaf(hv.y, a.y, sr);
                sr = fmaf(hv.z, a.z, sr);  sr = fmaf(hv.w, a.w, sr);
                sz = fmaf(hv.x, b.x, sz);  sz = fmaf(hv.y, b.y, sz);
                sz = fmaf(hv.z, b.z, sz);  sz = fmaf(hv.w, b.w, sz);
                sn = fmaf(hv.x, cc.x, sn); sn = fmaf(hv.y, cc.y, sn);
                sn = fmaf(hv.z, cc.z, sn); sn = fmaf(hv.w, cc.w, sn);
            }
            const float* ig = g_ig + (size_t)t * G3;
            float r = sigm(ig[i] + sr);
            float z = sigm(ig[HD + i] + sz);
            float n = tanhs(ig[2 * HD + i] + r * (sn + bn));
            float o = n + z * (h[i] - n);
            __syncthreads();
            y[(size_t)t * HD + i] = o;
        }
        __syncthreads();
    }
}

// ---------------- tail: final_state = y[T-1] ----------------
__global__ void k_tail(float* out, int T, long long out_size) {
    long long base = (long long)T * HD;
    if (out_size >= base + HD) {
        int i = threadIdx.x;
        out[base + i] = out[base - HD + i];
    }
}

// ---------------- launch ----------------
extern "C" void kernel_launch(void* const* d_in, const int* in_sizes, int n_in,
                              void* d_out, int out_size) {
    const float* x      = (const float*)d_in[0];
    const float* state  = (const float*)d_in[1];
    const int*   start  = (const int*)d_in[2];
    const float* Wih    = (const float*)d_in[4];
    const float* Whh    = (const float*)d_in[5];
    const float* bias   = (const float*)d_in[6];
    const float* bias_n = (const float*)d_in[7];
    float* out = (float*)d_out;

    int T = in_sizes[2];
    if (T > MAXT) T = MAXT;

    cudaFuncSetAttribute(k_ig, cudaFuncAttributeMaxDynamicSharedMemorySize, IG_SMEM);
    cudaFuncSetAttribute(k_hg2, cudaFuncAttributeMaxDynamicSharedMemorySize, HG2_SMEM);

    int n4 = T * HD / 4;
    k_split_x<<<(n4 + 255) / 256, 256>>>(x, n4);
    k_split_w<<<(G3 * HD + 255) / 256, 256>>>(Wih, Whh);
    k_setup<<<1, 1024>>>(start, T);
    k_ig<<<dim3(12, (T + 127) / 128), 256, IG_SMEM>>>(bias, T);
    k_gates0<<<2048, 256>>>(out, state, Whh, bias_n);
    for (int j = 1; j < RNDJ; j++) {
        int maxnj = T / (j + 1) + 1;
        k_hg2<<<dim3(4, (maxnj + 127) / 128), 256, HG2_SMEM>>>(out, bias_n, j);
    }
    k_finish<<<512, 256>>>(Whh, bias_n, out);
    k_tail<<<1, 256>>>(out, T, (long long)out_size);
}

// round 6
// speedup vs baseline: 1.9461x; 1.0907x over previous
#include <cuda_runtime.h>
#include <cuda_bf16.h>
#include <cstdint>
#include <math.h>

#define MAXT 65536
#define HD   256
#define G3   768
#define NRA  40
#define RNDJ 6        // rounds 0..5 batched; finisher handles j>=6

// ---------------- device scratch ----------------
__device__ float g_ig[(size_t)MAXT * G3];
__device__ __align__(16) __nv_bfloat16 g_xh[(size_t)MAXT * HD];
__device__ __align__(16) __nv_bfloat16 g_xl[(size_t)MAXT * HD];
__device__ __align__(16) __nv_bfloat16 g_wih_h[G3 * HD];
__device__ __align__(16) __nv_bfloat16 g_wih_l[G3 * HD];
__device__ __align__(16) __nv_bfloat16 g_wq_h[G3 * HD];   // Whh gate-interleaved split
__device__ __align__(16) __nv_bfloat16 g_wq_l[G3 * HD];
__device__ int g_starts[MAXT + 1];
__device__ int g_len[MAXT];
__device__ int g_sorted[MAXT];
__device__ int g_hist[MAXT + 2];
__device__ int g_suffix[MAXT + 2];
__device__ int g_off[MAXT + 2];
__device__ int g_nact[NRA + 2];
__device__ int g_nep;
__device__ int g_start0;

// ---------------- math helpers ----------------
__device__ __forceinline__ float sigm(float x) {
    x = fminf(15.f, fmaxf(-15.f, x));
    return 1.f / (1.f + __expf(-x));
}
__device__ __forceinline__ float tanhs(float x) {
    x = fminf(9.f, fmaxf(-9.f, x));
    float e = __expf(-2.f * x);
    return (1.f - e) / (1.f + e);
}
__device__ __forceinline__ uint32_t smem_u32(const void* p) {
    uint32_t a;
    asm("{ .reg .u64 t; cvta.to.shared.u64 t, %1; cvt.u32.u64 %0, t; }" : "=r"(a) : "l"(p));
    return a;
}
__device__ __forceinline__ void cpa16(uint32_t s, const void* g) {
    asm volatile("cp.async.cg.shared.global [%0], [%1], 16;"
                 :: "r"(s), "l"(g) : "memory");
}
#define CP_COMMIT() asm volatile("cp.async.commit_group;" ::: "memory")
#define CP_WAIT(n)  asm volatile("cp.async.wait_group %0;" :: "n"(n) : "memory")

__device__ __forceinline__ void ldsm4(uint32_t a, uint32_t* r) {
    asm volatile("ldmatrix.sync.aligned.m8n8.x4.shared.b16 {%0,%1,%2,%3}, [%4];"
                 : "=r"(r[0]), "=r"(r[1]), "=r"(r[2]), "=r"(r[3]) : "r"(a));
}
__device__ __forceinline__ void mma16816(float* c, const uint32_t* a,
                                         uint32_t b0, uint32_t b1) {
    asm volatile("mma.sync.aligned.m16n8k16.row.col.f32.bf16.bf16.f32 "
                 "{%0,%1,%2,%3}, {%4,%5,%6,%7}, {%8,%9}, {%0,%1,%2,%3};"
                 : "+f"(c[0]), "+f"(c[1]), "+f"(c[2]), "+f"(c[3])
                 : "r"(a[0]), "r"(a[1]), "r"(a[2]), "r"(a[3]), "r"(b0), "r"(b1));
}

// Fused 3-term chunk MMA. NG = number of 32-col B groups per warp.
// Layout: rows*128B, swizzle off = r*128 + ((u ^ (r&7))<<4), u = 16B unit.
template<int NG>
__device__ __forceinline__ void mma_fused(uint32_t ah, uint32_t al,
                                          uint32_t bh, uint32_t bl,
                                          float (&acc)[2][4 * NG][4],
                                          int lane, int wm, int wn) {
    int arow = wm * 32 + (lane & 7) + (((lane >> 3) & 1) << 3);
    int aks  = (lane >> 4) & 1;
    int axor = arow & 7;
    uint32_t ahB = ah + arow * 128, alB = al + arow * 128;
    int brow0 = (lane & 7) + (((lane >> 4) & 1) << 3);
    int bks  = (lane >> 3) & 1;
#pragma unroll
    for (int ks = 0; ks < 4; ks++) {
        uint32_t au = (uint32_t)(((2 * ks + aks) ^ axor) << 4);
        uint32_t AH0[4], AH1[4], AL0[4], AL1[4];
        ldsm4(ahB + au,        AH0);
        ldsm4(ahB + 2048 + au, AH1);
        ldsm4(alB + au,        AL0);
        ldsm4(alB + 2048 + au, AL1);
#pragma unroll
        for (int g = 0; g < NG; g++) {
            int brow = wn * (32 * NG) + g * 32 + brow0;
            int bxor = brow & 7;
            uint32_t bu = (uint32_t)(((2 * ks + bks) ^ bxor) << 4);
            uint32_t bb = (uint32_t)(brow * 128);
            uint32_t BH0[4], BH1[4], BL0[4], BL1[4];
            ldsm4(bh + bb + bu,        BH0);
            ldsm4(bh + bb + 2048 + bu, BH1);
            ldsm4(bl + bb + bu,        BL0);
            ldsm4(bl + bb + 2048 + bu, BL1);
            int nb = g * 4;
            mma16816(acc[0][nb+0], AH0, BH0[0], BH0[1]);
            mma16816(acc[0][nb+1], AH0, BH0[2], BH0[3]);
            mma16816(acc[0][nb+2], AH0, BH1[0], BH1[1]);
            mma16816(acc[0][nb+3], AH0, BH1[2], BH1[3]);
            mma16816(acc[1][nb+0], AH1, BH0[0], BH0[1]);
            mma16816(acc[1][nb+1], AH1, BH0[2], BH0[3]);
            mma16816(acc[1][nb+2], AH1, BH1[0], BH1[1]);
            mma16816(acc[1][nb+3], AH1, BH1[2], BH1[3]);
            mma16816(acc[0][nb+0], AH0, BL0[0], BL0[1]);
            mma16816(acc[0][nb+1], AH0, BL0[2], BL0[3]);
            mma16816(acc[0][nb+2], AH0, BL1[0], BL1[1]);
            mma16816(acc[0][nb+3], AH0, BL1[2], BL1[3]);
            mma16816(acc[1][nb+0], AH1, BL0[0], BL0[1]);
            mma16816(acc[1][nb+1], AH1, BL0[2], BL0[3]);
            mma16816(acc[1][nb+2], AH1, BL1[0], BL1[1]);
            mma16816(acc[1][nb+3], AH1, BL1[2], BL1[3]);
            mma16816(acc[0][nb+0], AL0, BH0[0], BH0[1]);
            mma16816(acc[0][nb+1], AL0, BH0[2], BH0[3]);
            mma16816(acc[0][nb+2], AL0, BH1[0], BH1[1]);
            mma16816(acc[0][nb+3], AL0, BH1[2], BH1[3]);
            mma16816(acc[1][nb+0], AL1, BH0[0], BH0[1]);
            mma16816(acc[1][nb+1], AL1, BH0[2], BH0[3]);
            mma16816(acc[1][nb+2], AL1, BH1[0], BH1[1]);
            mma16816(acc[1][nb+3], AL1, BH1[2], BH1[3]);
        }
    }
}

// ---------------- k_ig stage layout: 3 stages x 64KB (tile 128x128) ----------------
#define IGS_AH 0
#define IGS_AL 16384
#define IGS_BH 32768
#define IGS_BL 49152
#define IGS_STRIDE 65536
#define IG_SMEM (3 * IGS_STRIDE)
#define IG_CST 132            // C staging row stride (floats)

// ---------------- k_hg2: 2 stages (A32 32KB + BH 24KB + BL 24KB) + conv + s_t --
#define HG2_A32 0
#define HG2_BH  32768
#define HG2_BL  57344
#define HG2_STRIDE 81920
#define HG2_CAH 163840
#define HG2_CAL 180224
#define HG2_T   196608
#define HG2_SMEM 197120
#define CSTRIDE 196

// ---------------- merged split kernel ----------------
__global__ void k_split(const float* __restrict__ x, const float* __restrict__ wih,
                        const float* __restrict__ whh, int n4) {
    int b = blockIdx.x;
    if (b < G3) {   // weights: 768 blocks x 256 threads = G3*HD
        int i = b * 256 + threadIdx.x;
        float v = wih[i];
        __nv_bfloat16 h = __float2bfloat16(v);
        g_wih_h[i] = h;
        g_wih_l[i] = __float2bfloat16(v - __bfloat162float(h));
        int q = i >> 8, k = i & 255;
        int nt = q / 192, rem = q % 192;
        int gg = rem >> 6, il = rem & 63;
        float w = whh[(size_t)(gg * 256 + nt * 64 + il) * HD + k];
        __nv_bfloat16 hh = __float2bfloat16(w);
        g_wq_h[i] = hh;
        g_wq_l[i] = __float2bfloat16(w - __bfloat162float(hh));
    } else {
        int v = (b - G3) * 256 + threadIdx.x;
        if (v >= n4) return;
        float4 a = *(const float4*)(x + (size_t)v * 4);
        __nv_bfloat16 h0 = __float2bfloat16(a.x), h1 = __float2bfloat16(a.y);
        __nv_bfloat16 h2 = __float2bfloat16(a.z), h3 = __float2bfloat16(a.w);
        __nv_bfloat16 l0 = __float2bfloat16(a.x - __bfloat162float(h0));
        __nv_bfloat16 l1 = __float2bfloat16(a.y - __bfloat162float(h1));
        __nv_bfloat16 l2 = __float2bfloat16(a.z - __bfloat162float(h2));
        __nv_bfloat16 l3 = __float2bfloat16(a.w - __bfloat162float(h3));
        __nv_bfloat162* ph = (__nv_bfloat162*)(g_xh + (size_t)v * 4);
        __nv_bfloat162* pl = (__nv_bfloat162*)(g_xl + (size_t)v * 4);
        ph[0] = __halves2bfloat162(h0, h1); ph[1] = __halves2bfloat162(h2, h3);
        pl[0] = __halves2bfloat162(l0, l1); pl[1] = __halves2bfloat162(l2, l3);
    }
}

// ---------------- setup with shfl scans ----------------
__device__ __forceinline__ int warp_scan_incl(int v, int lane) {
#pragma unroll
    for (int o = 1; o < 32; o <<= 1) {
        int n = __shfl_up_sync(0xFFFFFFFFu, v, o);
        if (lane >= o) v += n;
    }
    return v;
}
__global__ void k_setup(const int* __restrict__ start, int T) {
    __shared__ int s_w[32];
    int tid = threadIdx.x, lane = tid & 31, w = tid >> 5;
    int per = (T + 1023) / 1024;
    int b0 = tid * per, b1 = min(T, b0 + per);

    int c = 0;
    for (int t = b0; t < b1; t++)
        if (t == 0 || start[t] != 0) c++;
    int inc = warp_scan_incl(c, lane);
    if (lane == 31) s_w[w] = inc;
    __syncthreads();
    if (w == 0) s_w[lane] = warp_scan_incl(s_w[lane], lane);
    __syncthreads();
    int excl = inc - c + (w ? s_w[w - 1] : 0);
    int nep = s_w[31];
    if (tid == 0) { g_nep = nep; g_start0 = (start[0] != 0); }

    int e = excl;
    for (int t = b0; t < b1; t++)
        if (t == 0 || start[t] != 0) g_starts[e++] = t;
    if (tid == 0) g_starts[nep] = T;
    __syncthreads();

    for (int b = tid; b <= T + 1; b += 1024) g_hist[b] = 0;
    __syncthreads();
    for (int e2 = tid; e2 < nep; e2 += 1024) {
        int L = g_starts[e2 + 1] - g_starts[e2];
        g_len[e2] = L;
        atomicAdd(&g_hist[L], 1);
    }
    __syncthreads();

    int NB = T + 2;
    int per2 = (NB + 1023) / 1024;
    int c0 = tid * per2, c1 = min(NB, c0 + per2);
    int s = 0;
    for (int b = c0; b < c1; b++) s += g_hist[b];
    int inc2 = warp_scan_incl(s, lane);
    if (lane == 31) s_w[w] = inc2;
    __syncthreads();
    if (w == 0) s_w[lane] = warp_scan_incl(s_w[lane], lane);
    __syncthreads();
    int incl_full = inc2 + (w ? s_w[w - 1] : 0);
    int total2 = s_w[31];
    int run = total2 - incl_full;
    for (int b = c1 - 1; b >= c0; b--) { run += g_hist[b]; g_suffix[b] = run; }
    __syncthreads();

    for (int b = tid; b <= T; b += 1024) g_off[b] = g_suffix[b + 1];
    for (int j = tid; j <= NRA; j += 1024) g_nact[j] = g_suffix[j + 1];
    __syncthreads();
    for (int e2 = tid; e2 < nep; e2 += 1024) {
        int L = g_len[e2];
        int p = atomicAdd(&g_off[L], 1);
        g_sorted[p] = e2;
    }
}

// ---------------- igates GEMM (3-stage cp.async, 128x128 tile, staged C) --------
__device__ __forceinline__ void ig_issue(uint32_t sb, int stage, int c,
                                         int m0, int n0, int tid) {
    uint32_t st = sb + stage * IGS_STRIDE;
    int cb = c * 64;
#pragma unroll
    for (int v = tid; v < 1024; v += 256) {
        int r = v >> 3, u = v & 7;
        uint32_t off = (uint32_t)(r * 128 + (((u ^ (r & 7))) << 4));
        size_t src = (size_t)(m0 + r) * HD + cb + u * 8;
        cpa16(st + IGS_AH + off, g_xh + src);
        cpa16(st + IGS_AL + off, g_xl + src);
    }
#pragma unroll
    for (int v = tid; v < 1024; v += 256) {
        int r = v >> 3, u = v & 7;
        uint32_t off = (uint32_t)(r * 128 + (((u ^ (r & 7))) << 4));
        size_t src = (size_t)(n0 + r) * HD + cb + u * 8;
        cpa16(st + IGS_BH + off, g_wih_h + src);
        cpa16(st + IGS_BL + off, g_wih_l + src);
    }
    CP_COMMIT();
}
__global__ void __launch_bounds__(256) k_ig(const float* __restrict__ bias, int T) {
    extern __shared__ __align__(128) char smem[];
    uint32_t sb = smem_u32(smem);
    int tid = threadIdx.x, lane = tid & 31, wid = tid >> 5;
    int wm = wid >> 1, wn = wid & 1;
    int n0 = blockIdx.x * 128, m0 = blockIdx.y * 128;

    float acc[2][8][4];
#pragma unroll
    for (int a = 0; a < 2; a++)
#pragma unroll
        for (int b = 0; b < 8; b++)
#pragma unroll
            for (int cdx = 0; cdx < 4; cdx++) acc[a][b][cdx] = 0.f;

    ig_issue(sb, 0, 0, m0, n0, tid);
    ig_issue(sb, 1, 1, m0, n0, tid);
    ig_issue(sb, 2, 2, m0, n0, tid);

    CP_WAIT(2); __syncthreads();
    {
        uint32_t st = sb;
        mma_fused<2>(st + IGS_AH, st + IGS_AL, st + IGS_BH, st + IGS_BL, acc, lane, wm, wn);
    }
    __syncthreads();
    ig_issue(sb, 0, 3, m0, n0, tid);

    CP_WAIT(2); __syncthreads();
    {
        uint32_t st = sb + IGS_STRIDE;
        mma_fused<2>(st + IGS_AH, st + IGS_AL, st + IGS_BH, st + IGS_BL, acc, lane, wm, wn);
    }
    CP_WAIT(1); __syncthreads();
    {
        uint32_t st = sb + 2 * IGS_STRIDE;
        mma_fused<2>(st + IGS_AH, st + IGS_AL, st + IGS_BH, st + IGS_BL, acc, lane, wm, wn);
    }
    CP_WAIT(0); __syncthreads();
    {
        uint32_t st = sb;
        mma_fused<2>(st + IGS_AH, st + IGS_AL, st + IGS_BH, st + IGS_BL, acc, lane, wm, wn);
    }
    __syncthreads();

    // stage C into smem (stage-1 region is free now), then coalesced stores
    float* C = (float*)(smem + IGS_STRIDE);
#pragma unroll
    for (int g = 0; g < 2; g++)
#pragma unroll
        for (int nt = 0; nt < 4; nt++) {
            int nb = g * 4 + nt;
            int col = wn * 64 + g * 32 + nt * 8 + (lane & 3) * 2;
#pragma unroll
            for (int mt = 0; mt < 2; mt++) {
                int row = wm * 32 + mt * 16 + (lane >> 2);
                *(float2*)&C[row * IG_CST + col] =
                    make_float2(acc[mt][nb][0], acc[mt][nb][1]);
                *(float2*)&C[(row + 8) * IG_CST + col] =
                    make_float2(acc[mt][nb][2], acc[mt][nb][3]);
            }
        }
    __syncthreads();
#pragma unroll
    for (int idx = tid; idx < 4096; idx += 256) {
        int row = idx >> 5, q = idx & 31;
        float4 cv = *(const float4*)&C[row * IG_CST + q * 4];
        float4 bv = *(const float4*)(bias + n0 + q * 4);
        *(float4*)(g_ig + (size_t)(m0 + row) * G3 + n0 + q * 4) =
            make_float4(cv.x + bv.x, cv.y + bv.y, cv.z + bv.z, cv.w + bv.w);
    }
}

// ---------------- fused round kernel: GEMM 128x192 + gate epilogue -> y ----------
__device__ __forceinline__ void hg2_issue(uint32_t sb, char* smem, int stage, int c,
                                          const float* y, int nt, int tid) {
    uint32_t st = sb + stage * HG2_STRIDE;
    const int* s_t = (const int*)(smem + HG2_T);
    int cb = c * 64;
#pragma unroll
    for (int v = tid; v < 2048; v += 256) {
        int r = v >> 4, u = v & 15;
        const float* src = y + (size_t)(s_t[r] - 1) * HD + cb + u * 4;
        cpa16(st + HG2_A32 + r * 256 + u * 16, src);
    }
#pragma unroll
    for (int v = tid; v < 1536; v += 256) {
        int r = v >> 3, u = v & 7;
        uint32_t off = (uint32_t)(r * 128 + (((u ^ (r & 7))) << 4));
        size_t src = (size_t)(nt * 192 + r) * HD + cb + u * 8;
        cpa16(st + HG2_BH + off, g_wq_h + src);
        cpa16(st + HG2_BL + off, g_wq_l + src);
    }
    CP_COMMIT();
}
__device__ __forceinline__ void hg2_convert(char* smem, int stage, int tid) {
    const float* a32 = (const float*)(smem + stage * HG2_STRIDE + HG2_A32);
#pragma unroll
    for (int v = tid; v < 1024; v += 256) {
        int r = v >> 3, u = v & 7;
        float4 f0 = *(const float4*)(a32 + r * 64 + u * 8);
        float4 f1 = *(const float4*)(a32 + r * 64 + u * 8 + 4);
        float fv[8] = {f0.x, f0.y, f0.z, f0.w, f1.x, f1.y, f1.z, f1.w};
        __nv_bfloat16 hi[8], lo[8];
#pragma unroll
        for (int q = 0; q < 8; q++) {
            hi[q] = __float2bfloat16(fv[q]);
            lo[q] = __float2bfloat16(fv[q] - __bfloat162float(hi[q]));
        }
        uint32_t off = (uint32_t)(r * 128 + (((u ^ (r & 7))) << 4));
        *(uint4*)(smem + HG2_CAH + off) = *(const uint4*)hi;
        *(uint4*)(smem + HG2_CAL + off) = *(const uint4*)lo;
    }
}
__global__ void __launch_bounds__(256) k_hg2(float* __restrict__ y,
                                             const float* __restrict__ bias_n, int j) {
    extern __shared__ __align__(128) char smem[];
    uint32_t sb = smem_u32(smem);
    int* s_t = (int*)(smem + HG2_T);
    int nj = g_nact[j];
    int mt0 = blockIdx.y * 128;
    if (mt0 >= nj) return;
    int tid = threadIdx.x, lane = tid & 31, wid = tid >> 5;
    int wm = wid >> 1, wn = wid & 1;
    int nt = blockIdx.x;   // unit block: units [nt*64, nt*64+64)

    if (tid < 128) {
        int m = mt0 + tid;
        s_t[tid] = (m < nj) ? (g_starts[g_sorted[m]] + j) : 1;
    }
    __syncthreads();

    float acc[2][12][4];
#pragma unroll
    for (int a = 0; a < 2; a++)
#pragma unroll
        for (int b = 0; b < 12; b++)
#pragma unroll
            for (int cdx = 0; cdx < 4; cdx++) acc[a][b][cdx] = 0.f;

    hg2_issue(sb, smem, 0, 0, y, nt, tid);
    hg2_issue(sb, smem, 1, 1, y, nt, tid);

    CP_WAIT(1); __syncthreads();
    hg2_convert(smem, 0, tid); __syncthreads();
    mma_fused<3>(sb + HG2_CAH, sb + HG2_CAL,
                 sb + 0 * HG2_STRIDE + HG2_BH, sb + 0 * HG2_STRIDE + HG2_BL,
                 acc, lane, wm, wn);
    __syncthreads();
    hg2_issue(sb, smem, 0, 2, y, nt, tid);

    CP_WAIT(1); __syncthreads();
    hg2_convert(smem, 1, tid); __syncthreads();
    mma_fused<3>(sb + HG2_CAH, sb + HG2_CAL,
                 sb + 1 * HG2_STRIDE + HG2_BH, sb + 1 * HG2_STRIDE + HG2_BL,
                 acc, lane, wm, wn);
    __syncthreads();
    hg2_issue(sb, smem, 1, 3, y, nt, tid);

    CP_WAIT(1); __syncthreads();
    hg2_convert(smem, 0, tid); __syncthreads();
    mma_fused<3>(sb + HG2_CAH, sb + HG2_CAL,
                 sb + 0 * HG2_STRIDE + HG2_BH, sb + 0 * HG2_STRIDE + HG2_BL,
                 acc, lane, wm, wn);

    CP_WAIT(0); __syncthreads();
    hg2_convert(smem, 1, tid); __syncthreads();
    mma_fused<3>(sb + HG2_CAH, sb + HG2_CAL,
                 sb + 1 * HG2_STRIDE + HG2_BH, sb + 1 * HG2_STRIDE + HG2_BL,
                 acc, lane, wm, wn);
    __syncthreads();

    // stage C (pre-activations) into smem [128][CSTRIDE]
    float* C = (float*)smem;
#pragma unroll
    for (int ntv = 0; ntv < 12; ntv++) {
        int g = ntv >> 2, ntl = ntv & 3;
        int col = wn * 96 + g * 32 + ntl * 8 + (lane & 3) * 2;
#pragma unroll
        for (int mt = 0; mt < 2; mt++) {
            int row = wm * 32 + mt * 16 + (lane >> 2);
            C[row * CSTRIDE + col]           = acc[mt][ntv][0];
            C[row * CSTRIDE + col + 1]       = acc[mt][ntv][1];
            C[(row + 8) * CSTRIDE + col]     = acc[mt][ntv][2];
            C[(row + 8) * CSTRIDE + col + 1] = acc[mt][ntv][3];
        }
    }
    __syncthreads();

    // gate epilogue: 128 rows x 64 units (float4 over units)
#pragma unroll 1
    for (int idx = tid; idx < 2048; idx += 256) {
        int row = idx >> 4, q4 = idx & 15;
        if (mt0 + row >= nj) continue;
        int t = s_t[row];
        int i = nt * 64 + q4 * 4;
        const float* cr = C + row * CSTRIDE + q4 * 4;
        float4 rp = *(const float4*)(cr);
        float4 zp = *(const float4*)(cr + 64);
        float4 np = *(const float4*)(cr + 128);
        const float* igrow = g_ig + (size_t)t * G3;
        float4 igr = *(const float4*)(igrow + i);
        float4 igz = *(const float4*)(igrow + HD + i);
        float4 ign = *(const float4*)(igrow + 2 * HD + i);
        float4 h4  = *(const float4*)(y + (size_t)(t - 1) * HD + i);
        float4 bn4 = *(const float4*)(bias_n + i);
        float rv[4] = {rp.x, rp.y, rp.z, rp.w};
        float zv[4] = {zp.x, zp.y, zp.z, zp.w};
        float nv[4] = {np.x, np.y, np.z, np.w};
        float ir[4] = {igr.x, igr.y, igr.z, igr.w};
        float iz[4] = {igz.x, igz.y, igz.z, igz.w};
        float in_[4] = {ign.x, ign.y, ign.z, ign.w};
        float hv[4] = {h4.x, h4.y, h4.z, h4.w};
        float bv[4] = {bn4.x, bn4.y, bn4.z, bn4.w};
        float o[4];
#pragma unroll
        for (int u = 0; u < 4; u++) {
            float r = sigm(ir[u] + rv[u]);
            float z = sigm(iz[u] + zv[u]);
            float n = tanhs(in_[u] + r * (nv[u] + bv[u]));
            o[u] = n + z * (hv[u] - n);
        }
        *(float4*)(y + (size_t)t * HD + i) = make_float4(o[0], o[1], o[2], o[3]);
    }
}

// ---------------- gates for round 0 ----------------
__global__ void __launch_bounds__(256) k_gates0(float* __restrict__ y,
                                                const float* __restrict__ state,
                                                const float* __restrict__ Whh,
                                                const float* __restrict__ bias_n) {
    int nj = g_nact[0];
    __shared__ float sh[HD];
    int i = threadIdx.x;
    for (int m = blockIdx.x; m < nj; m += gridDim.x) {
        int e = g_sorted[m];
        int t = g_starts[e];
        const float* ig = g_ig + (size_t)t * G3;
        float o;
        if (e == 0 && !g_start0) {
            sh[i] = state[i];
            __syncthreads();
            float sr = 0.f, sz = 0.f, sn = 0.f;
            const float4* h4 = (const float4*)sh;
            const float4* w0 = (const float4*)(Whh + (size_t)i * HD);
            const float4* w1 = (const float4*)(Whh + (size_t)(HD + i) * HD);
            const float4* w2 = (const float4*)(Whh + (size_t)(2 * HD + i) * HD);
#pragma unroll 8
            for (int k = 0; k < 64; k++) {
                float4 hv = h4[k];
                float4 a = w0[k], b = w1[k], cc = w2[k];
                sr = fmaf(hv.x, a.x, sr);  sr = fmaf(hv.y, a.y, sr);
                sr = fmaf(hv.z, a.z, sr);  sr = fmaf(hv.w, a.w, sr);
                sz = fmaf(hv.x, b.x, sz);  sz = fmaf(hv.y, b.y, sz);
                sz = fmaf(hv.z, b.z, sz);  sz = fmaf(hv.w, b.w, sz);
                sn = fmaf(hv.x, cc.x, sn); sn = fmaf(hv.y, cc.y, sn);
                sn = fmaf(hv.z, cc.z, sn); sn = fmaf(hv.w, cc.w, sn);
            }
            float h = sh[i];
            float r = sigm(ig[i] + sr);
            float z = sigm(ig[HD + i] + sz);
            float n = tanhs(ig[2 * HD + i] + r * (sn + bias_n[i]));
            o = n + z * (h - n);
            __syncthreads();
        } else {
            float r = sigm(ig[i]);
            float z = sigm(ig[HD + i]);
            float n = tanhs(ig[2 * HD + i] + r * bias_n[i]);
            o = n * (1.f - z);
        }
        y[(size_t)t * HD + i] = o;
    }
}

// ---------------- finisher: episodes with len > RNDJ ----------------
__global__ void __launch_bounds__(256) k_finish(const float* __restrict__ Whh,
                                                const float* __restrict__ bias_n,
                                                float* y) {
    int nover = g_nact[RNDJ];
    __shared__ __align__(16) float h[HD];
    int i = threadIdx.x;
    const float4* w0 = (const float4*)(Whh + (size_t)i * HD);
    const float4* w1 = (const float4*)(Whh + (size_t)(HD + i) * HD);
    const float4* w2 = (const float4*)(Whh + (size_t)(2 * HD + i) * HD);
    float bn = bias_n[i];
    for (int idx = blockIdx.x; idx < nover; idx += gridDim.x) {
        int e = g_sorted[idx];
        int ts = g_starts[e], L = g_len[e];
        for (int j = RNDJ; j < L; j++) {
            int t = ts + j;
            h[i] = y[(size_t)(t - 1) * HD + i];
            __syncthreads();
            const float4* h4 = (const float4*)h;
            float sr = 0.f, sz = 0.f, sn = 0.f;
#pragma unroll 8
            for (int k = 0; k < 64; k++) {
                float4 hv = h4[k];
                float4 a = w0[k], b = w1[k], cc = w2[k];
                sr = fmaf(hv.x, a.x, sr);  sr = fmaf(hv.y, a.y, sr);
                sr = fmaf(hv.z, a.z, sr);  sr = fmaf(hv.w, a.w, sr);
                sz = fmaf(hv.x, b.x, sz);  sz = fmaf(hv.y, b.y, sz);
                sz = fmaf(hv.z, b.z, sz);  sz = fmaf(hv.w, b.w, sz);
                sn = fmaf(hv.x, cc.x, sn); sn = fmaf(hv.y, cc.y, sn);
                sn = fmaf(hv.z, cc.z, sn); sn = fmaf(hv.w, cc.w, sn);
            }
            const float* ig = g_ig + (size_t)t * G3;
            float r = sigm(ig[i] + sr);
            float z = sigm(ig[HD + i] + sz);
            float n = tanhs(ig[2 * HD + i] + r * (sn + bn));
            float o = n + z * (h[i] - n);
            __syncthreads();
            y[(size_t)t * HD + i] = o;
        }
        __syncthreads();
    }
}

// ---------------- tail: final_state = y[T-1] ----------------
__global__ void k_tail(float* out, int T, long long out_size) {
    long long base = (long long)T * HD;
    if (out_size >= base + HD) {
        int i = threadIdx.x;
        out[base + i] = out[base - HD + i];
    }
}

// ---------------- launch ----------------
extern "C" void kernel_launch(void* const* d_in, const int* in_sizes, int n_in,
                              void* d_out, int out_size) {
    const float* x      = (const float*)d_in[0];
    const float* state  = (const float*)d_in[1];
    const int*   start  = (const int*)d_in[2];
    const float* Wih    = (const float*)d_in[4];
    const float* Whh    = (const float*)d_in[5];
    const float* bias   = (const float*)d_in[6];
    const float* bias_n = (const float*)d_in[7];
    float* out = (float*)d_out;

    int T = in_sizes[2];
    if (T > MAXT) T = MAXT;

    cudaFuncSetAttribute(k_ig, cudaFuncAttributeMaxDynamicSharedMemorySize, IG_SMEM);
    cudaFuncSetAttribute(k_hg2, cudaFuncAttributeMaxDynamicSharedMemorySize, HG2_SMEM);

    int n4 = T * HD / 4;
    k_split<<<G3 + (n4 + 255) / 256, 256>>>(x, Wih, Whh, n4);
    k_setup<<<1, 1024>>>(start, T);
    k_ig<<<dim3(6, (T + 127) / 128), 256, IG_SMEM>>>(bias, T);
    k_gates0<<<8192, 256>>>(out, state, Whh, bias_n);
    for (int j = 1; j < RNDJ; j++) {
        int maxnj = T / (j + 1) + 1;
        k_hg2<<<dim3(4, (maxnj + 127) / 128), 256, HG2_SMEM>>>(out, bias_n, j);
    }
    k_finish<<<2048, 256>>>(Whh, bias_n, out);
    k_tail<<<1, 256>>>(out, T, (long long)out_size);
}

// round 7
// speedup vs baseline: 2.1831x; 1.1218x over previous
#include <cuda_runtime.h>
#include <cuda_bf16.h>
#include <cstdint>
#include <math.h>

#define MAXT 65536
#define HD   256
#define G3   768
#define NRA  40
#define RNDJ 6        // rounds 0..5 batched; finisher handles j>=6
#define HBINS 2048

// ---------------- device scratch ----------------
__device__ float g_ig[(size_t)MAXT * G3];
__device__ __align__(16) __nv_bfloat16 g_xh[(size_t)MAXT * HD];
__device__ __align__(16) __nv_bfloat16 g_xl[(size_t)MAXT * HD];
__device__ __align__(16) __nv_bfloat16 g_wih_h[G3 * HD];
__device__ __align__(16) __nv_bfloat16 g_wih_l[G3 * HD];
__device__ __align__(16) __nv_bfloat16 g_wq_h[G3 * HD];   // Whh gate-interleaved split
__device__ __align__(16) __nv_bfloat16 g_wq_l[G3 * HD];
__device__ int g_starts[MAXT + 1];
__device__ int g_len[MAXT];
__device__ int g_sorted[MAXT];
__device__ int g_hist[MAXT + 2];
__device__ int g_suffix[MAXT + 2];
__device__ int g_off[MAXT + 2];
__device__ int g_nact[NRA + 2];
__device__ int g_nep;
__device__ int g_start0;

// ---------------- math helpers ----------------
__device__ __forceinline__ float sigm(float x) {
    x = fminf(15.f, fmaxf(-15.f, x));
    return 1.f / (1.f + __expf(-x));
}
__device__ __forceinline__ float tanhs(float x) {
    x = fminf(9.f, fmaxf(-9.f, x));
    float e = __expf(-2.f * x);
    return (1.f - e) / (1.f + e);
}
__device__ __forceinline__ uint32_t smem_u32(const void* p) {
    uint32_t a;
    asm("{ .reg .u64 t; cvta.to.shared.u64 t, %1; cvt.u32.u64 %0, t; }" : "=r"(a) : "l"(p));
    return a;
}
__device__ __forceinline__ void cpa16(uint32_t s, const void* g) {
    asm volatile("cp.async.cg.shared.global [%0], [%1], 16;"
                 :: "r"(s), "l"(g) : "memory");
}
#define CP_COMMIT() asm volatile("cp.async.commit_group;" ::: "memory")
#define CP_WAIT(n)  asm volatile("cp.async.wait_group %0;" :: "n"(n) : "memory")

__device__ __forceinline__ void ldsm4(uint32_t a, uint32_t* r) {
    asm volatile("ldmatrix.sync.aligned.m8n8.x4.shared.b16 {%0,%1,%2,%3}, [%4];"
                 : "=r"(r[0]), "=r"(r[1]), "=r"(r[2]), "=r"(r[3]) : "r"(a));
}
__device__ __forceinline__ void mma16816(float* c, const uint32_t* a,
                                         uint32_t b0, uint32_t b1) {
    asm volatile("mma.sync.aligned.m16n8k16.row.col.f32.bf16.bf16.f32 "
                 "{%0,%1,%2,%3}, {%4,%5,%6,%7}, {%8,%9}, {%0,%1,%2,%3};"
                 : "+f"(c[0]), "+f"(c[1]), "+f"(c[2]), "+f"(c[3])
                 : "r"(a[0]), "r"(a[1]), "r"(a[2]), "r"(a[3]), "r"(b0), "r"(b1));
}

// Fused 3-term chunk MMA. NG = number of 32-col B groups per warp.
template<int NG>
__device__ __forceinline__ void mma_fused(uint32_t ah, uint32_t al,
                                          uint32_t bh, uint32_t bl,
                                          float (&acc)[2][4 * NG][4],
                                          int lane, int wm, int wn) {
    int arow = wm * 32 + (lane & 7) + (((lane >> 3) & 1) << 3);
    int aks  = (lane >> 4) & 1;
    int axor = arow & 7;
    uint32_t ahB = ah + arow * 128, alB = al + arow * 128;
    int brow0 = (lane & 7) + (((lane >> 4) & 1) << 3);
    int bks  = (lane >> 3) & 1;
#pragma unroll
    for (int ks = 0; ks < 4; ks++) {
        uint32_t au = (uint32_t)(((2 * ks + aks) ^ axor) << 4);
        uint32_t AH0[4], AH1[4], AL0[4], AL1[4];
        ldsm4(ahB + au,        AH0);
        ldsm4(ahB + 2048 + au, AH1);
        ldsm4(alB + au,        AL0);
        ldsm4(alB + 2048 + au, AL1);
#pragma unroll
        for (int g = 0; g < NG; g++) {
            int brow = wn * (32 * NG) + g * 32 + brow0;
            int bxor = brow & 7;
            uint32_t bu = (uint32_t)(((2 * ks + bks) ^ bxor) << 4);
            uint32_t bb = (uint32_t)(brow * 128);
            uint32_t BH0[4], BH1[4], BL0[4], BL1[4];
            ldsm4(bh + bb + bu,        BH0);
            ldsm4(bh + bb + 2048 + bu, BH1);
            ldsm4(bl + bb + bu,        BL0);
            ldsm4(bl + bb + 2048 + bu, BL1);
            int nb = g * 4;
            mma16816(acc[0][nb+0], AH0, BH0[0], BH0[1]);
            mma16816(acc[0][nb+1], AH0, BH0[2], BH0[3]);
            mma16816(acc[0][nb+2], AH0, BH1[0], BH1[1]);
            mma16816(acc[0][nb+3], AH0, BH1[2], BH1[3]);
            mma16816(acc[1][nb+0], AH1, BH0[0], BH0[1]);
            mma16816(acc[1][nb+1], AH1, BH0[2], BH0[3]);
            mma16816(acc[1][nb+2], AH1, BH1[0], BH1[1]);
            mma16816(acc[1][nb+3], AH1, BH1[2], BH1[3]);
            mma16816(acc[0][nb+0], AH0, BL0[0], BL0[1]);
            mma16816(acc[0][nb+1], AH0, BL0[2], BL0[3]);
            mma16816(acc[0][nb+2], AH0, BL1[0], BL1[1]);
            mma16816(acc[0][nb+3], AH0, BL1[2], BL1[3]);
            mma16816(acc[1][nb+0], AH1, BL0[0], BL0[1]);
            mma16816(acc[1][nb+1], AH1, BL0[2], BL0[3]);
            mma16816(acc[1][nb+2], AH1, BL1[0], BL1[1]);
            mma16816(acc[1][nb+3], AH1, BL1[2], BL1[3]);
            mma16816(acc[0][nb+0], AL0, BH0[0], BH0[1]);
            mma16816(acc[0][nb+1], AL0, BH0[2], BH0[3]);
            mma16816(acc[0][nb+2], AL0, BH1[0], BH1[1]);
            mma16816(acc[0][nb+3], AL0, BH1[2], BH1[3]);
            mma16816(acc[1][nb+0], AL1, BH0[0], BH0[1]);
            mma16816(acc[1][nb+1], AL1, BH0[2], BH0[3]);
            mma16816(acc[1][nb+2], AL1, BH1[0], BH1[1]);
            mma16816(acc[1][nb+3], AL1, BH1[2], BH1[3]);
        }
    }
}

// ---------------- k_ig stage layout: 2 stages x 48KB (tile 128x64, 2 CTAs/SM) -----
#define IGS_AH 0
#define IGS_AL 16384
#define IGS_BH 32768
#define IGS_BL 40960
#define IGS_STRIDE 49152
#define IG_SMEM (2 * IGS_STRIDE)
#define IG_CST 68            // C staging row stride (floats)

// ---------------- k_hg2: 2 stages (A32 32KB + BH 24KB + BL 24KB) + conv + s_t --
#define HG2_A32 0
#define HG2_BH  32768
#define HG2_BL  57344
#define HG2_STRIDE 81920
#define HG2_CAH 163840
#define HG2_CAL 180224
#define HG2_T   196608
#define HG2_SMEM 197120
#define CSTRIDE 196

// ---------------- merged split kernel ----------------
__global__ void k_split(const float* __restrict__ x, const float* __restrict__ wih,
                        const float* __restrict__ whh, int n4) {
    int b = blockIdx.x;
    if (b < G3) {
        int i = b * 256 + threadIdx.x;
        float v = wih[i];
        __nv_bfloat16 h = __float2bfloat16(v);
        g_wih_h[i] = h;
        g_wih_l[i] = __float2bfloat16(v - __bfloat162float(h));
        int q = i >> 8, k = i & 255;
        int nt = q / 192, rem = q % 192;
        int gg = rem >> 6, il = rem & 63;
        float w = whh[(size_t)(gg * 256 + nt * 64 + il) * HD + k];
        __nv_bfloat16 hh = __float2bfloat16(w);
        g_wq_h[i] = hh;
        g_wq_l[i] = __float2bfloat16(w - __bfloat162float(hh));
    } else {
        int v = (b - G3) * 256 + threadIdx.x;
        if (v >= n4) return;
        float4 a = *(const float4*)(x + (size_t)v * 4);
        __nv_bfloat16 h0 = __float2bfloat16(a.x), h1 = __float2bfloat16(a.y);
        __nv_bfloat16 h2 = __float2bfloat16(a.z), h3 = __float2bfloat16(a.w);
        __nv_bfloat16 l0 = __float2bfloat16(a.x - __bfloat162float(h0));
        __nv_bfloat16 l1 = __float2bfloat16(a.y - __bfloat162float(h1));
        __nv_bfloat16 l2 = __float2bfloat16(a.z - __bfloat162float(h2));
        __nv_bfloat16 l3 = __float2bfloat16(a.w - __bfloat162float(h3));
        __nv_bfloat162* ph = (__nv_bfloat162*)(g_xh + (size_t)v * 4);
        __nv_bfloat162* pl = (__nv_bfloat162*)(g_xl + (size_t)v * 4);
        ph[0] = __halves2bfloat162(h0, h1); ph[1] = __halves2bfloat162(h2, h3);
        pl[0] = __halves2bfloat162(l0, l1); pl[1] = __halves2bfloat162(l2, l3);
    }
}

// ---------------- setup (shfl scans + bounded smem histogram) ----------------
__device__ __forceinline__ int warp_scan_incl(int v, int lane) {
#pragma unroll
    for (int o = 1; o < 32; o <<= 1) {
        int n = __shfl_up_sync(0xFFFFFFFFu, v, o);
        if (lane >= o) v += n;
    }
    return v;
}
__global__ void k_setup(const int* __restrict__ start, int T) {
    __shared__ int s_w[32];
    __shared__ int s_hist[HBINS];
    __shared__ int s_lmax;
    int tid = threadIdx.x, lane = tid & 31, w = tid >> 5;
    int per = (T + 1023) / 1024;
    int b0 = tid * per, b1 = min(T, b0 + per);

    int c = 0;
    for (int t = b0; t < b1; t++)
        if (t == 0 || start[t] != 0) c++;
    int inc = warp_scan_incl(c, lane);
    if (lane == 31) s_w[w] = inc;
    __syncthreads();
    if (w == 0) s_w[lane] = warp_scan_incl(s_w[lane], lane);
    __syncthreads();
    int excl = inc - c + (w ? s_w[w - 1] : 0);
    int nep = s_w[31];
    if (tid == 0) { g_nep = nep; g_start0 = (start[0] != 0); s_lmax = 0; }

    int e = excl;
    for (int t = b0; t < b1; t++)
        if (t == 0 || start[t] != 0) g_starts[e++] = t;
    if (tid == 0) g_starts[nep] = T;
    for (int b = tid; b < HBINS; b += 1024) s_hist[b] = 0;
    __syncthreads();

    // pass 1: lengths, smem hist (<HBINS), Lmax
    for (int e2 = tid; e2 < nep; e2 += 1024) {
        int L = g_starts[e2 + 1] - g_starts[e2];
        g_len[e2] = L;
        if (L < HBINS) atomicAdd(&s_hist[L], 1);
        atomicMax(&s_lmax, L);
    }
    __syncthreads();
    int Lmax = s_lmax;
    int NB = Lmax + 2;

    // clear global bins [0, NB), merge smem hist, add rare big lengths
    for (int b = tid; b < NB; b += 1024) g_hist[b] = 0;
    __syncthreads();
    for (int b = tid; b < min(NB, HBINS); b += 1024)
        if (s_hist[b]) g_hist[b] = s_hist[b];
    if (Lmax >= HBINS) {
        __syncthreads();
        for (int e2 = tid; e2 < nep; e2 += 1024) {
            int L = g_len[e2];
            if (L >= HBINS) atomicAdd(&g_hist[L], 1);
        }
    }
    __syncthreads();

    // suffix over [0, NB)
    int per2 = (NB + 1023) / 1024;
    int c0 = tid * per2, c1 = min(NB, c0 + per2);
    int s = 0;
    for (int b = c0; b < c1; b++) s += g_hist[b];
    int inc2 = warp_scan_incl(s, lane);
    if (lane == 31) s_w[w] = inc2;
    __syncthreads();
    if (w == 0) s_w[lane] = warp_scan_incl(s_w[lane], lane);
    __syncthreads();
    int incl_full = inc2 + (w ? s_w[w - 1] : 0);
    int total2 = s_w[31];
    int run = total2 - incl_full;
    for (int b = c1 - 1; b >= c0; b--) { run += g_hist[b]; g_suffix[b] = run; }
    __syncthreads();

    for (int b = tid; b <= Lmax; b += 1024) g_off[b] = g_suffix[b + 1];
    for (int j = tid; j <= NRA; j += 1024)
        g_nact[j] = (j + 1 <= Lmax + 1) ? g_suffix[j + 1] : 0;
    __syncthreads();
    for (int e2 = tid; e2 < nep; e2 += 1024) {
        int L = g_len[e2];
        int p = atomicAdd(&g_off[L], 1);
        g_sorted[p] = e2;
    }
}

// ---------------- igates GEMM (2-stage, 128x64 tile, 2 CTAs/SM) ----------------
__device__ __forceinline__ void ig_issue(uint32_t sb, int stage, int c,
                                         int m0, int n0, int T, int tid) {
    uint32_t st = sb + stage * IGS_STRIDE;
    int cb = c * 64;
#pragma unroll
    for (int v = tid; v < 1024; v += 256) {
        int r = v >> 3, u = v & 7;
        int row = min(m0 + r, T - 1);
        uint32_t off = (uint32_t)(r * 128 + (((u ^ (r & 7))) << 4));
        size_t src = (size_t)row * HD + cb + u * 8;
        cpa16(st + IGS_AH + off, g_xh + src);
        cpa16(st + IGS_AL + off, g_xl + src);
    }
#pragma unroll
    for (int v = tid; v < 512; v += 256) {
        int r = v >> 3, u = v & 7;
        uint32_t off = (uint32_t)(r * 128 + (((u ^ (r & 7))) << 4));
        size_t src = (size_t)(n0 + r) * HD + cb + u * 8;
        cpa16(st + IGS_BH + off, g_wih_h + src);
        cpa16(st + IGS_BL + off, g_wih_l + src);
    }
    CP_COMMIT();
}
__global__ void __launch_bounds__(256, 2) k_ig(const float* __restrict__ bias, int T) {
    extern __shared__ __align__(128) char smem[];
    uint32_t sb = smem_u32(smem);
    int tid = threadIdx.x, lane = tid & 31, wid = tid >> 5;
    int wm = wid >> 1, wn = wid & 1;
    int n0 = blockIdx.x * 64, m0 = blockIdx.y * 128;

    float acc[2][4][4];
#pragma unroll
    for (int a = 0; a < 2; a++)
#pragma unroll
        for (int b = 0; b < 4; b++)
#pragma unroll
            for (int cdx = 0; cdx < 4; cdx++) acc[a][b][cdx] = 0.f;

    ig_issue(sb, 0, 0, m0, n0, T, tid);
    ig_issue(sb, 1, 1, m0, n0, T, tid);

    CP_WAIT(1); __syncthreads();
    {
        uint32_t st = sb;
        mma_fused<1>(st + IGS_AH, st + IGS_AL, st + IGS_BH, st + IGS_BL, acc, lane, wm, wn);
    }
    __syncthreads();
    ig_issue(sb, 0, 2, m0, n0, T, tid);

    CP_WAIT(1); __syncthreads();
    {
        uint32_t st = sb + IGS_STRIDE;
        mma_fused<1>(st + IGS_AH, st + IGS_AL, st + IGS_BH, st + IGS_BL, acc, lane, wm, wn);
    }
    __syncthreads();
    ig_issue(sb, 1, 3, m0, n0, T, tid);

    CP_WAIT(1); __syncthreads();
    {
        uint32_t st = sb;
        mma_fused<1>(st + IGS_AH, st + IGS_AL, st + IGS_BH, st + IGS_BL, acc, lane, wm, wn);
    }
    CP_WAIT(0); __syncthreads();
    {
        uint32_t st = sb + IGS_STRIDE;
        mma_fused<1>(st + IGS_AH, st + IGS_AL, st + IGS_BH, st + IGS_BL, acc, lane, wm, wn);
    }
    __syncthreads();

    // stage C in stage-0 smem, then coalesced stores
    float* C = (float*)smem;
#pragma unroll
    for (int nt = 0; nt < 4; nt++) {
        int col = wn * 32 + nt * 8 + (lane & 3) * 2;
#pragma unroll
        for (int mt = 0; mt < 2; mt++) {
            int row = wm * 32 + mt * 16 + (lane >> 2);
            *(float2*)&C[row * IG_CST + col] =
                make_float2(acc[mt][nt][0], acc[mt][nt][1]);
            *(float2*)&C[(row + 8) * IG_CST + col] =
                make_float2(acc[mt][nt][2], acc[mt][nt][3]);
        }
    }
    __syncthreads();
#pragma unroll
    for (int idx = tid; idx < 2048; idx += 256) {
        int row = idx >> 4, q = idx & 15;
        if (m0 + row >= T) continue;
        float4 cv = *(const float4*)&C[row * IG_CST + q * 4];
        float4 bv = *(const float4*)(bias + n0 + q * 4);
        *(float4*)(g_ig + (size_t)(m0 + row) * G3 + n0 + q * 4) =
            make_float4(cv.x + bv.x, cv.y + bv.y, cv.z + bv.z, cv.w + bv.w);
    }
}

// ---------------- fused round kernel: GEMM 128x192 + gate epilogue -> y ----------
__device__ __forceinline__ void hg2_issue(uint32_t sb, char* smem, int stage, int c,
                                          const float* y, int nt, int tid) {
    uint32_t st = sb + stage * HG2_STRIDE;
    const int* s_t = (const int*)(smem + HG2_T);
    int cb = c * 64;
#pragma unroll
    for (int v = tid; v < 2048; v += 256) {
        int r = v >> 4, u = v & 15;
        const float* src = y + (size_t)(s_t[r] - 1) * HD + cb + u * 4;
        cpa16(st + HG2_A32 + r * 256 + u * 16, src);
    }
#pragma unroll
    for (int v = tid; v < 1536; v += 256) {
        int r = v >> 3, u = v & 7;
        uint32_t off = (uint32_t)(r * 128 + (((u ^ (r & 7))) << 4));
        size_t src = (size_t)(nt * 192 + r) * HD + cb + u * 8;
        cpa16(st + HG2_BH + off, g_wq_h + src);
        cpa16(st + HG2_BL + off, g_wq_l + src);
    }
    CP_COMMIT();
}
__device__ __forceinline__ void hg2_convert(char* smem, int stage, int tid) {
    const float* a32 = (const float*)(smem + stage * HG2_STRIDE + HG2_A32);
#pragma unroll
    for (int v = tid; v < 1024; v += 256) {
        int r = v >> 3, u = v & 7;
        float4 f0 = *(const float4*)(a32 + r * 64 + u * 8);
        float4 f1 = *(const float4*)(a32 + r * 64 + u * 8 + 4);
        float fv[8] = {f0.x, f0.y, f0.z, f0.w, f1.x, f1.y, f1.z, f1.w};
        __nv_bfloat16 hi[8], lo[8];
#pragma unroll
        for (int q = 0; q < 8; q++) {
            hi[q] = __float2bfloat16(fv[q]);
            lo[q] = __float2bfloat16(fv[q] - __bfloat162float(hi[q]));
        }
        uint32_t off = (uint32_t)(r * 128 + (((u ^ (r & 7))) << 4));
        *(uint4*)(smem + HG2_CAH + off) = *(const uint4*)hi;
        *(uint4*)(smem + HG2_CAL + off) = *(const uint4*)lo;
    }
}
__global__ void __launch_bounds__(256) k_hg2(float* __restrict__ y,
                                             const float* __restrict__ bias_n, int j) {
    extern __shared__ __align__(128) char smem[];
    uint32_t sb = smem_u32(smem);
    int* s_t = (int*)(smem + HG2_T);
    int nj = g_nact[j];
    int mt0 = blockIdx.y * 128;
    if (mt0 >= nj) return;
    int tid = threadIdx.x, lane = tid & 31, wid = tid >> 5;
    int wm = wid >> 1, wn = wid & 1;
    int nt = blockIdx.x;

    if (tid < 128) {
        int m = mt0 + tid;
        s_t[tid] = (m < nj) ? (g_starts[g_sorted[m]] + j) : 1;
    }
    __syncthreads();

    float acc[2][12][4];
#pragma unroll
    for (int a = 0; a < 2; a++)
#pragma unroll
        for (int b = 0; b < 12; b++)
#pragma unroll
            for (int cdx = 0; cdx < 4; cdx++) acc[a][b][cdx] = 0.f;

    hg2_issue(sb, smem, 0, 0, y, nt, tid);
    hg2_issue(sb, smem, 1, 1, y, nt, tid);

    CP_WAIT(1); __syncthreads();
    hg2_convert(smem, 0, tid); __syncthreads();
    mma_fused<3>(sb + HG2_CAH, sb + HG2_CAL,
                 sb + 0 * HG2_STRIDE + HG2_BH, sb + 0 * HG2_STRIDE + HG2_BL,
                 acc, lane, wm, wn);
    __syncthreads();
    hg2_issue(sb, smem, 0, 2, y, nt, tid);

    CP_WAIT(1); __syncthreads();
    hg2_convert(smem, 1, tid); __syncthreads();
    mma_fused<3>(sb + HG2_CAH, sb + HG2_CAL,
                 sb + 1 * HG2_STRIDE + HG2_BH, sb + 1 * HG2_STRIDE + HG2_BL,
                 acc, lane, wm, wn);
    __syncthreads();
    hg2_issue(sb, smem, 1, 3, y, nt, tid);

    CP_WAIT(1); __syncthreads();
    hg2_convert(smem, 0, tid); __syncthreads();
    mma_fused<3>(sb + HG2_CAH, sb + HG2_CAL,
                 sb + 0 * HG2_STRIDE + HG2_BH, sb + 0 * HG2_STRIDE + HG2_BL,
                 acc, lane, wm, wn);

    CP_WAIT(0); __syncthreads();
    hg2_convert(smem, 1, tid); __syncthreads();
    mma_fused<3>(sb + HG2_CAH, sb + HG2_CAL,
                 sb + 1 * HG2_STRIDE + HG2_BH, sb + 1 * HG2_STRIDE + HG2_BL,
                 acc, lane, wm, wn);
    __syncthreads();

    float* C = (float*)smem;
#pragma unroll
    for (int ntv = 0; ntv < 12; ntv++) {
        int g = ntv >> 2, ntl = ntv & 3;
        int col = wn * 96 + g * 32 + ntl * 8 + (lane & 3) * 2;
#pragma unroll
        for (int mt = 0; mt < 2; mt++) {
            int row = wm * 32 + mt * 16 + (lane >> 2);
            C[row * CSTRIDE + col]           = acc[mt][ntv][0];
            C[row * CSTRIDE + col + 1]       = acc[mt][ntv][1];
            C[(row + 8) * CSTRIDE + col]     = acc[mt][ntv][2];
            C[(row + 8) * CSTRIDE + col + 1] = acc[mt][ntv][3];
        }
    }
    __syncthreads();

#pragma unroll 1
    for (int idx = tid; idx < 2048; idx += 256) {
        int row = idx >> 4, q4 = idx & 15;
        if (mt0 + row >= nj) continue;
        int t = s_t[row];
        int i = nt * 64 + q4 * 4;
        const float* cr = C + row * CSTRIDE + q4 * 4;
        float4 rp = *(const float4*)(cr);
        float4 zp = *(const float4*)(cr + 64);
        float4 np = *(const float4*)(cr + 128);
        const float* igrow = g_ig + (size_t)t * G3;
        float4 igr = *(const float4*)(igrow + i);
        float4 igz = *(const float4*)(igrow + HD + i);
        float4 ign = *(const float4*)(igrow + 2 * HD + i);
        float4 h4  = *(const float4*)(y + (size_t)(t - 1) * HD + i);
        float4 bn4 = *(const float4*)(bias_n + i);
        float rv[4] = {rp.x, rp.y, rp.z, rp.w};
        float zv[4] = {zp.x, zp.y, zp.z, zp.w};
        float nv[4] = {np.x, np.y, np.z, np.w};
        float ir[4] = {igr.x, igr.y, igr.z, igr.w};
        float iz[4] = {igz.x, igz.y, igz.z, igz.w};
        float in_[4] = {ign.x, ign.y, ign.z, ign.w};
        float hv[4] = {h4.x, h4.y, h4.z, h4.w};
        float bv[4] = {bn4.x, bn4.y, bn4.z, bn4.w};
        float o[4];
#pragma unroll
        for (int u = 0; u < 4; u++) {
            float r = sigm(ir[u] + rv[u]);
            float z = sigm(iz[u] + zv[u]);
            float n = tanhs(in_[u] + r * (nv[u] + bv[u]));
            o[u] = n + z * (hv[u] - n);
        }
        *(float4*)(y + (size_t)t * HD + i) = make_float4(o[0], o[1], o[2], o[3]);
    }
}

// ---------------- episode-0 round-0 (h = state) ----------------
__global__ void k_ep0(float* __restrict__ y, const float* __restrict__ state,
                      const float* __restrict__ Whh, const float* __restrict__ bias_n) {
    if (g_start0) return;   // handled by flat kernel (h=0)
    __shared__ float sh[HD];
    int i = threadIdx.x;
    sh[i] = state[i];
    __syncthreads();
    const float4* h4 = (const float4*)sh;
    const float4* w0 = (const float4*)(Whh + (size_t)i * HD);
    const float4* w1 = (const float4*)(Whh + (size_t)(HD + i) * HD);
    const float4* w2 = (const float4*)(Whh + (size_t)(2 * HD + i) * HD);
    float sr = 0.f, sz = 0.f, sn = 0.f;
#pragma unroll 8
    for (int k = 0; k < 64; k++) {
        float4 hv = h4[k];
        float4 a = w0[k], b = w1[k], cc = w2[k];
        sr = fmaf(hv.x, a.x, sr);  sr = fmaf(hv.y, a.y, sr);
        sr = fmaf(hv.z, a.z, sr);  sr = fmaf(hv.w, a.w, sr);
        sz = fmaf(hv.x, b.x, sz);  sz = fmaf(hv.y, b.y, sz);
        sz = fmaf(hv.z, b.z, sz);  sz = fmaf(hv.w, b.w, sz);
        sn = fmaf(hv.x, cc.x, sn); sn = fmaf(hv.y, cc.y, sn);
        sn = fmaf(hv.z, cc.z, sn); sn = fmaf(hv.w, cc.w, sn);
    }
    const float* ig = g_ig;   // t = 0
    float h = sh[i];
    float r = sigm(ig[i] + sr);
    float z = sigm(ig[HD + i] + sz);
    float n = tanhs(ig[2 * HD + i] + r * (sn + bias_n[i]));
    y[i] = n + z * (h - n);
}

// ---------------- flat round-0 gates (h = 0) ----------------
__global__ void __launch_bounds__(256) k_gates0f(float* __restrict__ y,
                                                 const float* __restrict__ bias_n) {
    int nj = g_nact[0];
    int rloc = threadIdx.x >> 6;          // row in block 0..3
    int q = (threadIdx.x & 63) * 4;       // unit
    float4 bn4 = *(const float4*)(bias_n + q);
    for (int base = blockIdx.x * 4; base < nj; base += gridDim.x * 4) {
        int m = base + rloc;
        if (m >= nj) continue;
        int e = g_sorted[m];
        if (e == 0 && !g_start0) continue;   // k_ep0 handles
        int t = g_starts[e];
        const float* ig = g_ig + (size_t)t * G3;
        float4 ir = *(const float4*)(ig + q);
        float4 iz = *(const float4*)(ig + HD + q);
        float4 in4 = *(const float4*)(ig + 2 * HD + q);
        float irv[4] = {ir.x, ir.y, ir.z, ir.w};
        float izv[4] = {iz.x, iz.y, iz.z, iz.w};
        float inv[4] = {in4.x, in4.y, in4.z, in4.w};
        float bnv[4] = {bn4.x, bn4.y, bn4.z, bn4.w};
        float o[4];
#pragma unroll
        for (int u = 0; u < 4; u++) {
            float r = sigm(irv[u]);
            float z = sigm(izv[u]);
            float n = tanhs(inv[u] + r * bnv[u]);
            o[u] = n * (1.f - z);
        }
        *(float4*)(y + (size_t)t * HD + q) = make_float4(o[0], o[1], o[2], o[3]);
    }
}

// ---------------- finisher: episodes with len > RNDJ ----------------
__global__ void __launch_bounds__(256) k_finish(const float* __restrict__ Whh,
                                                const float* __restrict__ bias_n,
                                                float* y) {
    int nover = g_nact[RNDJ];
    __shared__ __align__(16) float h[HD];
    int i = threadIdx.x;
    const float4* w0 = (const float4*)(Whh + (size_t)i * HD);
    const float4* w1 = (const float4*)(Whh + (size_t)(HD + i) * HD);
    const float4* w2 = (const float4*)(Whh + (size_t)(2 * HD + i) * HD);
    float bn = bias_n[i];
    for (int idx = blockIdx.x; idx < nover; idx += gridDim.x) {
        int e = g_sorted[idx];
        int ts = g_starts[e], L = g_len[e];
        for (int j = RNDJ; j < L; j++) {
            int t = ts + j;
            h[i] = y[(size_t)(t - 1) * HD + i];
            __syncthreads();
            const float4* h4 = (const float4*)h;
            float sr = 0.f, sz = 0.f, sn = 0.f;
#pragma unroll 8
            for (int k = 0; k < 64; k++) {
                float4 hv = h4[k];
                float4 a = w0[k], b = w1[k], cc = w2[k];
                sr = fmaf(hv.x, a.x, sr);  sr = fmaf(hv.y, a.y, sr);
                sr = fmaf(hv.z, a.z, sr);  sr = fmaf(hv.w, a.w, sr);
                sz = fmaf(hv.x, b.x, sz);  sz = fmaf(hv.y, b.y, sz);
                sz = fmaf(hv.z, b.z, sz);  sz = fmaf(hv.w, b.w, sz);
                sn = fmaf(hv.x, cc.x, sn); sn = fmaf(hv.y, cc.y, sn);
                sn = fmaf(hv.z, cc.z, sn); sn = fmaf(hv.w, cc.w, sn);
            }
            const float* ig = g_ig + (size_t)t * G3;
            float r = sigm(ig[i] + sr);
            float z = sigm(ig[HD + i] + sz);
            float n = tanhs(ig[2 * HD + i] + r * (sn + bn));
            float o = n + z * (h[i] - n);
            __syncthreads();
            y[(size_t)t * HD + i] = o;
        }
        __syncthreads();
    }
}

// ---------------- tail: final_state = y[T-1] ----------------
__global__ void k_tail(float* out, int T, long long out_size) {
    long long base = (long long)T * HD;
    if (out_size >= base + HD) {
        int i = threadIdx.x;
        out[base + i] = out[base - HD + i];
    }
}

// ---------------- launch ----------------
extern "C" void kernel_launch(void* const* d_in, const int* in_sizes, int n_in,
                              void* d_out, int out_size) {
    const float* x      = (const float*)d_in[0];
    const float* state  = (const float*)d_in[1];
    const int*   start  = (const int*)d_in[2];
    const float* Wih    = (const float*)d_in[4];
    const float* Whh    = (const float*)d_in[5];
    const float* bias   = (const float*)d_in[6];
    const float* bias_n = (const float*)d_in[7];
    float* out = (float*)d_out;

    int T = in_sizes[2];
    if (T > MAXT) T = MAXT;

    cudaFuncSetAttribute(k_ig, cudaFuncAttributeMaxDynamicSharedMemorySize, IG_SMEM);
    cudaFuncSetAttribute(k_hg2, cudaFuncAttributeMaxDynamicSharedMemorySize, HG2_SMEM);

    int n4 = T * HD / 4;
    k_split<<<G3 + (n4 + 255) / 256, 256>>>(x, Wih, Whh, n4);
    k_setup<<<1, 1024>>>(start, T);
    k_ig<<<dim3(12, (T + 127) / 128), 256, IG_SMEM>>>(bias, T);
    k_ep0<<<1, 256>>>(out, state, Whh, bias_n);
    k_gates0f<<<8192, 256>>>(out, bias_n);
    for (int j = 1; j < RNDJ; j++) {
        int maxnj = T / (j + 1) + 1;
        k_hg2<<<dim3(4, (maxnj + 127) / 128), 256, HG2_SMEM>>>(out, bias_n, j);
    }
    k_finish<<<2048, 256>>>(Whh, bias_n, out);
    k_tail<<<1, 256>>>(out, T, (long long)out_size);
}